// round 12
// baseline (speedup 1.0000x reference)
#include <cuda_runtime.h>
#include <cuda_fp16.h>
#include <cstdint>

// Problem dims
#define BB 16384
#define FF 128
#define HH 1024
#define NSTEPS 6

// ---------------- scratch (static __device__, no allocation) ----------------
// Weights [K][N] row-major
__device__ __align__(16) __half g_W1x[256 * HH];           // [256][1024] hi;lo
__device__ __align__(16) __half g_W2x[(size_t)HH * HH];    // [1024][1024] hi only
__device__ __align__(16) __half g_W3x[(size_t)2048 * FF];  // [2048][128] hi;lo (L3 primal)
__device__ __align__(16) __half g_W3T[256 * HH];           // [256][1024] hi;lo of W3^T (Y)
// Activations, single copies (logical K duplication via masked addressing)
__device__ __align__(16) __half g_eps[(size_t)BB * FF];
__device__ __align__(16) __half g_XS [(size_t)BB * FF];
__device__ __align__(16) __half g_H1p[(size_t)BB * HH];
__device__ __align__(16) __half g_H1t[(size_t)BB * HH];
__device__ __align__(16) __half g_H2p[(size_t)BB * HH];
// constants for the tangent path, fp16
__device__ __align__(16) __half g_T1[(size_t)BB * HH];     // eps @ W1
__device__ __align__(16) __half g_Y [(size_t)BB * HH];     // eps @ W3^T
// fp32 state
__device__ float g_tracep[(size_t)8 * BB]; // per-n-CTA trace partials (deterministic)
__device__ float g_xcur[BB * FF];
__device__ float g_accX[BB * FF];
__device__ float g_accL[BB];
__device__ float g_logdet[BB];

// ---------------- helpers ----------------
__device__ __forceinline__ uint32_t smem_u32(const void* p) {
    return (uint32_t)__cvta_generic_to_shared(p);
}
__device__ __forceinline__ void cp16(uint32_t s, const void* g) {
    asm volatile("cp.async.cg.shared.global [%0], [%1], 16;\n" :: "r"(s), "l"(g));
}
__device__ __forceinline__ void cp_commit() { asm volatile("cp.async.commit_group;\n"); }
__device__ __forceinline__ void cp_wait0()  { asm volatile("cp.async.wait_group 0;\n"); }
__device__ __forceinline__ void cp_wait1()  { asm volatile("cp.async.wait_group 1;\n"); }

__device__ __forceinline__ void ldsm4(uint32_t* r, uint32_t a) {
    asm volatile("ldmatrix.sync.aligned.m8n8.x4.shared.b16 {%0,%1,%2,%3},[%4];"
                 : "=r"(r[0]), "=r"(r[1]), "=r"(r[2]), "=r"(r[3]) : "r"(a));
}
__device__ __forceinline__ void ldsm4t(uint32_t* r, uint32_t a) {
    asm volatile("ldmatrix.sync.aligned.m8n8.x4.trans.shared.b16 {%0,%1,%2,%3},[%4];"
                 : "=r"(r[0]), "=r"(r[1]), "=r"(r[2]), "=r"(r[3]) : "r"(a));
}
__device__ __forceinline__ void mma16816(float* c, const uint32_t* a, uint32_t b0, uint32_t b1) {
    asm volatile(
        "mma.sync.aligned.m16n8k16.row.col.f32.f16.f16.f32 "
        "{%0,%1,%2,%3},{%4,%5,%6,%7},{%8,%9},{%0,%1,%2,%3};"
        : "+f"(c[0]), "+f"(c[1]), "+f"(c[2]), "+f"(c[3])
        : "r"(a[0]), "r"(a[1]), "r"(a[2]), "r"(a[3]), "r"(b0), "r"(b1));
}
__device__ __forceinline__ uint32_t h2pack(float a, float b) {
    __half2 t = __floats2half2_rn(a, b);
    return *reinterpret_cast<uint32_t*>(&t);
}
__device__ __forceinline__ void h2unpack(uint32_t v, float& a, float& b) {
    __half2 t = *reinterpret_cast<__half2*>(&v);
    a = __half2float(__low2half(t));
    b = __half2float(__high2half(t));
}

// ---------------- kernel ids ----------------
enum { E_T1 = 0, E_Y, E_L1, E_L2F, E_L3P };

// ---------------- fused GEMM core ----------------
// 256 threads, 8 warps (2 x 4), warp tile (BMT/2)x32, mma m16n8k16, BK=64.
// BMT=128 for single-accum kernels (halves B reload traffic); 64 for dual L2F
// (register-pinned) and L3P (keeps grid >= SM count).
constexpr int BN = 128, BK = 64, NSTG = 3;
constexpr int LDA_S = BK + 8;          // 72
constexpr int LDB_S = BN + 8;          // 136
constexpr int B_STG = BK * LDB_S;      // 8704
constexpr int SM_BIG  = NSTG * (128 * LDA_S + B_STG) * 2;      // 107520 B (BMT=128 single)
constexpr int SM_DUAL = NSTG * (2 * 64 * LDA_S + B_STG) * 2;   // 107520 B (BMT=64 dual)
constexpr int SM_L3   = NSTG * (64 * LDA_S + B_STG) * 2;       // 79872 B  (BMT=64 single)

template <int EPI>
__global__ __launch_bounds__(256, 2)
void gemm_k(const float* __restrict__ bias, const float* __restrict__ w1t,
            float tval, float h, int st) {
    constexpr bool DUAL = (EPI == E_L2F);
    constexpr int BMT = (EPI == E_L2F || EPI == E_L3P) ? 64 : 128;
    constexpr int MF  = BMT / 32;                               // m-frags per warp
    constexpr int A_STG = BMT * LDA_S;
    constexpr int Nd = (EPI == E_L3P) ? FF : HH;
    constexpr int Kd = (EPI == E_T1 || EPI == E_Y || EPI == E_L1) ? 256 :
                       (EPI == E_L2F) ? 1024 : 2048;            // logical K
    constexpr int LDA_G = (EPI == E_T1 || EPI == E_Y || EPI == E_L1) ? FF : HH;
    constexpr int KMASK = LDA_G - 1;

    const __half* Ap =
        (EPI == E_T1 || EPI == E_Y) ? g_eps :
        (EPI == E_L1) ? g_XS :
        (EPI == E_L2F) ? g_H1p : g_H2p;
    const __half* At = g_H1t;                                  // DUAL only
    const __half* Bg =
        (EPI == E_T1 || EPI == E_L1) ? g_W1x :
        (EPI == E_Y) ? g_W3T :
        (EPI == E_L2F) ? g_W2x : g_W3x;

    extern __shared__ __align__(16) __half smdyn[];
    __half* sAp = smdyn;                                   // [NSTG][BMT][LDA_S]
    __half* sAt = smdyn + NSTG * A_STG;                    // DUAL only
    __half* sB  = smdyn + (DUAL ? 2 : 1) * NSTG * A_STG;   // [NSTG][BK][LDB_S]
    __shared__ float rsum[4][64];

    const int tid = threadIdx.x, lane = tid & 31, warp = tid >> 5;
    const int m0 = blockIdx.y * BMT, n0 = blockIdx.x * BN;
    const int wm = (warp & 1) * (BMT / 2), wn = (warp >> 1) * 32;

    float cp[MF][4][4];
    float ct[DUAL ? MF : 1][4][4];
#pragma unroll
    for (int i = 0; i < MF; i++)
#pragma unroll
        for (int j = 0; j < 4; j++)
#pragma unroll
            for (int k = 0; k < 4; k++) {
                cp[i][j][k] = 0.f;
                if (DUAL) ct[i][j][k] = 0.f;
            }

    auto pf = [&](int kt, int bufi) {
        const int k0 = kt * BK;
        __half* dAp = sAp + bufi * A_STG;
        __half* dB  = sB + bufi * B_STG;
#pragma unroll
        for (int i = 0; i < MF; i++) {         // A: BMT*8 chunks of 8 halves
            int ch = tid + 256 * i;
            int r = ch >> 3, c8 = (ch & 7) * 8;
            int kg = (k0 + c8) & KMASK;
            cp16(smem_u32(dAp + r * LDA_S + c8), Ap + (size_t)(m0 + r) * LDA_G + kg);
            if (DUAL)
                cp16(smem_u32(sAt + bufi * A_STG + r * LDA_S + c8),
                     At + (size_t)(m0 + r) * LDA_G + kg);
        }
#pragma unroll
        for (int i = 0; i < 4; i++) {          // B: 1024 chunks
            int ch = tid + 256 * i;
            int r = ch >> 4, c8 = (ch & 15) * 8;
            cp16(smem_u32(dB + r * LDB_S + c8), Bg + (size_t)(k0 + r) * Nd + n0 + c8);
        }
        cp_commit();
    };

    const int nk = Kd / BK;
    pf(0, 0);
    pf(1, 1);
    for (int kt = 0; kt < nk; kt++) {
        const int buf = kt % NSTG;
        if (kt == nk - 1) cp_wait0(); else cp_wait1();
        __syncthreads();
        if (kt + 2 < nk) pf(kt + 2, (kt + 2) % NSTG);

        const __half* cAp = sAp + buf * A_STG;
        const __half* cAt = sAt + buf * A_STG;
        const __half* cB  = sB + buf * B_STG;
#pragma unroll
        for (int kk = 0; kk < BK; kk += 16) {
            uint32_t a[MF][4], at_[DUAL ? MF : 1][4], b[2][4];
#pragma unroll
            for (int mf = 0; mf < MF; mf++) {
                uint32_t off = (wm + mf * 16 + (lane & 15)) * LDA_S + kk + ((lane >> 4) << 3);
                ldsm4(a[mf], smem_u32(cAp + off));
                if (DUAL) ldsm4(at_[mf], smem_u32(cAt + off));
            }
#pragma unroll
            for (int nb = 0; nb < 2; nb++)
                ldsm4t(b[nb], smem_u32(cB + (kk + (lane & 7) + ((lane >> 3) & 1) * 8) * LDB_S
                                          + wn + nb * 16 + ((lane >> 4) << 3)));
#pragma unroll
            for (int mf = 0; mf < MF; mf++)
#pragma unroll
                for (int ns = 0; ns < 4; ns++) {
                    mma16816(cp[mf][ns], a[mf], b[ns >> 1][(ns & 1) * 2],
                             b[ns >> 1][(ns & 1) * 2 + 1]);
                    if (DUAL)
                        mma16816(ct[mf][ns], at_[mf], b[ns >> 1][(ns & 1) * 2],
                                 b[ns >> 1][(ns & 1) * 2 + 1]);
                }
        }
    }

    // ---------------- epilogues ----------------
    const int g = lane >> 2, tig = lane & 3;

    if (EPI == E_L3P) {
        // RK logdet update from completed trace partials (written by L2F)
        if (tid < BMT) {
            int row = m0 + tid;
            float tr = 0.f;
#pragma unroll
            for (int cix = 0; cix < 8; cix++) tr += g_tracep[(size_t)cix * BB + row];
            if (st == 0)      g_accL[row] = tr;
            else if (st < 3)  g_accL[row] += 2.f * tr;
            else              g_logdet[row] -= (h / 6.f) * (g_accL[row] + tr);
        }
        // primal dx + fused RK state update
#pragma unroll
        for (int mf = 0; mf < MF; mf++)
#pragma unroll
            for (int ns = 0; ns < 4; ns++) {
                int col = wn + ns * 8 + tig * 2;
                int r0 = m0 + wm + mf * 16 + g;
#pragma unroll
                for (int half_ = 0; half_ < 2; half_++) {
                    int r = r0 + half_ * 8;
#pragma unroll
                    for (int j = 0; j < 2; j++) {
                        float k = cp[mf][ns][half_ * 2 + j] + bias[col + j];
                        size_t i = (size_t)r * FF + col + j;
                        float xc = g_xcur[i];
                        float xs;
                        if (st == 0)      { g_accX[i] = k;         xs = xc + 0.5f * h * k; }
                        else if (st == 1) { g_accX[i] += 2.f * k;  xs = xc + 0.5f * h * k; }
                        else if (st == 2) { g_accX[i] += 2.f * k;  xs = xc + h * k; }
                        else {
                            float xn = xc + (h / 6.f) * (g_accX[i] + k);
                            g_xcur[i] = xn;
                            xs = xn;
                        }
                        g_XS[i] = __float2half(xs);
                    }
                }
            }
        return;
    }

    if (EPI == E_L2F) {
        float tacc[MF][2];
#pragma unroll
        for (int i = 0; i < MF; i++) { tacc[i][0] = 0.f; tacc[i][1] = 0.f; }
#pragma unroll
        for (int mf = 0; mf < MF; mf++)
#pragma unroll
            for (int ns = 0; ns < 4; ns++) {
                int col = n0 + wn + ns * 8 + tig * 2;
                int r0 = m0 + wm + mf * 16 + g;
#pragma unroll
                for (int half_ = 0; half_ < 2; half_++) {
                    int r = r0 + half_ * 8;
                    size_t ob = (size_t)r * HH + col;
                    float h0 = tanhf(cp[mf][ns][half_ * 2 + 0] + bias[col]);
                    float h1 = tanhf(cp[mf][ns][half_ * 2 + 1] + bias[col + 1]);
                    *(uint32_t*)(g_H2p + ob) = h2pack(h0, h1);
                    float u0 = ct[mf][ns][half_ * 2 + 0] * (1.f - h0 * h0);
                    float u1 = ct[mf][ns][half_ * 2 + 1] * (1.f - h1 * h1);
                    float y0, y1;
                    h2unpack(*(const uint32_t*)(g_Y + ob), y0, y1);
                    tacc[mf][half_] += u0 * y0 + u1 * y1;
                }
            }
        // deterministic trace reduction: quad-shfl -> shared -> global partial
#pragma unroll
        for (int mf = 0; mf < MF; mf++)
#pragma unroll
            for (int half_ = 0; half_ < 2; half_++) {
                float s = tacc[mf][half_];
                s += __shfl_xor_sync(0xffffffffu, s, 1);
                s += __shfl_xor_sync(0xffffffffu, s, 2);
                if (tig == 0) rsum[warp >> 1][wm + mf * 16 + half_ * 8 + g] = s;
            }
        __syncthreads();
        if (tid < BMT) {
            float t = rsum[0][tid] + rsum[1][tid] + rsum[2][tid] + rsum[3][tid];
            g_tracep[(size_t)blockIdx.x * BB + m0 + tid] = t;
        }
        return;
    }

#pragma unroll
    for (int mf = 0; mf < MF; mf++)
#pragma unroll
        for (int ns = 0; ns < 4; ns++) {
            int col = n0 + wn + ns * 8 + tig * 2;
            int r0 = m0 + wm + mf * 16 + g;
#pragma unroll
            for (int half_ = 0; half_ < 2; half_++) {
                int r = r0 + half_ * 8;
                float v0 = cp[mf][ns][half_ * 2 + 0];
                float v1 = cp[mf][ns][half_ * 2 + 1];
                if (EPI == E_T1 || EPI == E_Y) {
                    __half* dst = (EPI == E_T1) ? g_T1 : g_Y;
                    size_t idx = (size_t)r * HH + col;
                    *(uint32_t*)(dst + idx) = h2pack(v0, v1);
                } else {  // E_L1
                    size_t ob = (size_t)r * HH + col;
                    float h0 = tanhf(v0 + tval * w1t[col] + bias[col]);
                    float h1 = tanhf(v1 + tval * w1t[col + 1] + bias[col + 1]);
                    *(uint32_t*)(g_H1p + ob) = h2pack(h0, h1);
                    float t0, t1;
                    h2unpack(*(const uint32_t*)(g_T1 + ob), t0, t1);
                    float u0 = (1.f - h0 * h0) * t0;
                    float u1 = (1.f - h1 * h1) * t1;
                    *(uint32_t*)(g_H1t + ob) = h2pack(u0, u1);
                }
            }
        }
}

// ---------------- setup / output ----------------
__global__ void setup_k(const float* __restrict__ x, const float* __restrict__ eps,
                        const float* __restrict__ W1, const float* __restrict__ W2,
                        const float* __restrict__ W3) {
    int i = blockIdx.x * blockDim.x + threadIdx.x;
    if (i < BB * FF) {
        float v = x[i];
        g_xcur[i] = v;
        g_XS[i]  = __float2half(v);
        g_eps[i] = __float2half(eps[i]);   // +-1 exact
    }
    if (i < BB) g_logdet[i] = 0.f;
    if (i < FF * HH) {                 // W1 rows 0..127 -> [256][1024] hi;lo
        int k = i / HH, n = i % HH;
        float w = W1[i];
        __half wh = __float2half(w);
        __half wl = __float2half(w - __half2float(wh));
        g_W1x[(size_t)k * HH + n]        = wh;
        g_W1x[(size_t)(k + FF) * HH + n] = wl;
    }
    if (i < HH * HH) {                 // W2 hi only
        g_W2x[i] = __float2half(W2[i]);
    }
    if (i < HH * FF) {                 // W3 [1024][128]
        int r3 = i / FF, c3 = i % FF;
        float w = W3[i];
        __half wh = __float2half(w);
        __half wl = __float2half(w - __half2float(wh));
        // L3 primal B: [2048][128] hi;lo
        g_W3x[(size_t)r3 * FF + c3]          = wh;
        g_W3x[(size_t)(r3 + HH) * FF + c3]   = wl;
        // Y B = W3^T: [256][1024] hi;lo
        g_W3T[(size_t)c3 * HH + r3]          = wh;
        g_W3T[(size_t)(c3 + FF) * HH + r3]   = wl;
    }
}

__global__ void finish_k(float* __restrict__ out) {
    int i = blockIdx.x * blockDim.x + threadIdx.x;
    if (i < BB * FF) out[i] = g_xcur[i];
    if (i < BB) out[BB * FF + i] = g_logdet[i];
}

// ---------------- launch ----------------
extern "C" void kernel_launch(void* const* d_in, const int* in_sizes, int n_in,
                              void* d_out, int out_size) {
    const float* x   = (const float*)d_in[0];
    const float* eps = (const float*)d_in[1];
    const float* W1  = (const float*)d_in[2];
    const float* b1  = (const float*)d_in[3];
    const float* W2  = (const float*)d_in[4];
    const float* b2  = (const float*)d_in[5];
    const float* W3  = (const float*)d_in[6];
    const float* b3  = (const float*)d_in[7];
    float* out = (float*)d_out;

    static bool attr_done = false;
    if (!attr_done) {
        cudaFuncSetAttribute(gemm_k<E_T1>,  cudaFuncAttributeMaxDynamicSharedMemorySize, SM_BIG);
        cudaFuncSetAttribute(gemm_k<E_Y>,   cudaFuncAttributeMaxDynamicSharedMemorySize, SM_BIG);
        cudaFuncSetAttribute(gemm_k<E_L1>,  cudaFuncAttributeMaxDynamicSharedMemorySize, SM_BIG);
        cudaFuncSetAttribute(gemm_k<E_L2F>, cudaFuncAttributeMaxDynamicSharedMemorySize, SM_DUAL);
        cudaFuncSetAttribute(gemm_k<E_L3P>, cudaFuncAttributeMaxDynamicSharedMemorySize, SM_L3);
        attr_done = true;
    }

    const int ew = (BB * FF + 255) / 256;
    setup_k<<<ew, 256>>>(x, eps, W1, W2, W3);

    const float h = 1.0f / NSTEPS;
    const float stc[4] = {0.f, 0.5f, 0.5f, 1.f};
    const float* w1t = W1 + FF * HH;   // W1 row 128 (time column), fp32

    // Constants: T1 = eps @ W1, Y = eps @ W3^T (exact weights via hi;lo split; fp16 stores)
    gemm_k<E_T1><<<dim3(8, BB / 128), 256, SM_BIG>>>(nullptr, nullptr, 0.f, h, 0);
    gemm_k<E_Y> <<<dim3(8, BB / 128), 256, SM_BIG>>>(nullptr, nullptr, 0.f, h, 0);

    for (int s = 0; s < NSTEPS; s++) {
        float t0 = s * h;
        for (int st = 0; st < 4; st++) {
            float tv = t0 + stc[st] * h;
            gemm_k<E_L1> <<<dim3(8, BB / 128), 256, SM_BIG>>>(b1, w1t, tv, h, st);
            gemm_k<E_L2F><<<dim3(8, BB / 64), 256, SM_DUAL>>>(b2, nullptr, 0.f, h, st);
            gemm_k<E_L3P><<<dim3(1, BB / 64), 256, SM_L3>>>(b3, nullptr, 0.f, h, st);
        }
    }
    finish_k<<<ew, 256>>>(out);
}

// round 13
// speedup vs baseline: 1.0030x; 1.0030x over previous
#include <cuda_runtime.h>
#include <cuda_fp16.h>
#include <cstdint>

// Problem dims
#define BB 16384
#define FF 128
#define HH 1024
#define NSTEPS 6

// ---------------- scratch (static __device__, no allocation) ----------------
__device__ __align__(16) __half g_W1x[256 * HH];           // [256][1024] hi;lo
__device__ __align__(16) __half g_W2x[(size_t)HH * HH];    // [1024][1024] hi only
__device__ __align__(16) __half g_W3x[(size_t)2048 * FF];  // [2048][128] hi;lo (L3 primal)
__device__ __align__(16) __half g_W3T[256 * HH];           // [256][1024] hi;lo of W3^T (Y)
__device__ __align__(16) __half g_eps[(size_t)BB * FF];
__device__ __align__(16) __half g_XS [(size_t)BB * FF];    // only for the initial L1
__device__ __align__(16) __half g_H1p[(size_t)BB * HH];
__device__ __align__(16) __half g_H1t[(size_t)BB * HH];
__device__ __align__(16) __half g_H2p[(size_t)BB * HH];
__device__ __align__(16) __half g_T1[(size_t)BB * HH];     // eps @ W1 (fp16)
__device__ __align__(16) __half g_Y [(size_t)BB * HH];     // eps @ W3^T (fp16)
__device__ float g_tracep[(size_t)8 * BB];
__device__ float g_xcur[BB * FF];
__device__ float g_accX[BB * FF];
__device__ float g_accL[BB];
__device__ float g_logdet[BB];

// ---------------- helpers ----------------
__device__ __forceinline__ uint32_t smem_u32(const void* p) {
    return (uint32_t)__cvta_generic_to_shared(p);
}
__device__ __forceinline__ void cp16(uint32_t s, const void* g) {
    asm volatile("cp.async.cg.shared.global [%0], [%1], 16;\n" :: "r"(s), "l"(g));
}
__device__ __forceinline__ void cp_commit() { asm volatile("cp.async.commit_group;\n"); }
__device__ __forceinline__ void cp_wait0()  { asm volatile("cp.async.wait_group 0;\n"); }
__device__ __forceinline__ void cp_wait1()  { asm volatile("cp.async.wait_group 1;\n"); }

__device__ __forceinline__ void ldsm4(uint32_t* r, uint32_t a) {
    asm volatile("ldmatrix.sync.aligned.m8n8.x4.shared.b16 {%0,%1,%2,%3},[%4];"
                 : "=r"(r[0]), "=r"(r[1]), "=r"(r[2]), "=r"(r[3]) : "r"(a));
}
__device__ __forceinline__ void ldsm4t(uint32_t* r, uint32_t a) {
    asm volatile("ldmatrix.sync.aligned.m8n8.x4.trans.shared.b16 {%0,%1,%2,%3},[%4];"
                 : "=r"(r[0]), "=r"(r[1]), "=r"(r[2]), "=r"(r[3]) : "r"(a));
}
__device__ __forceinline__ void mma16816(float* c, const uint32_t* a, uint32_t b0, uint32_t b1) {
    asm volatile(
        "mma.sync.aligned.m16n8k16.row.col.f32.f16.f16.f32 "
        "{%0,%1,%2,%3},{%4,%5,%6,%7},{%8,%9},{%0,%1,%2,%3};"
        : "+f"(c[0]), "+f"(c[1]), "+f"(c[2]), "+f"(c[3])
        : "r"(a[0]), "r"(a[1]), "r"(a[2]), "r"(a[3]), "r"(b0), "r"(b1));
}
__device__ __forceinline__ uint32_t h2pack(float a, float b) {
    __half2 t = __floats2half2_rn(a, b);
    return *reinterpret_cast<uint32_t*>(&t);
}
__device__ __forceinline__ void h2unpack(uint32_t v, float& a, float& b) {
    __half2 t = *reinterpret_cast<__half2*>(&v);
    a = __half2float(__low2half(t));
    b = __half2float(__high2half(t));
}

// ---------------- kernel ids ----------------
enum { E_T1 = 0, E_Y, E_L1, E_L2F };

// ---------------- shared tiling constants ----------------
constexpr int BN = 128, BK = 64, NSTG = 3;
constexpr int LDA_S = BK + 8;          // 72
constexpr int LDB_S = BN + 8;          // 136
constexpr int A64   = 64 * LDA_S;      // 4608 halves
constexpr int B_STG = BK * LDB_S;      // 8704 halves
constexpr int SM_SINGLE = NSTG * (A64 + B_STG) * 2;       // 79872 B
constexpr int SM_DUAL   = NSTG * (2 * A64 + B_STG) * 2;   // 107520 B

// ---------------- generic GEMM (T1 / Y / initial L1 / fused L2) ----------------
template <int EPI>
__global__ __launch_bounds__(256, 2)
void gemm_k(const float* __restrict__ bias, const float* __restrict__ w1t,
            float tval, float h, int st) {
    constexpr bool DUAL = (EPI == E_L2F);
    constexpr int Kd = (EPI == E_L2F) ? 1024 : 256;          // logical K
    constexpr int LDA_G = (EPI == E_L2F) ? HH : FF;
    constexpr int KMASK = LDA_G - 1;

    const __half* Ap =
        (EPI == E_T1 || EPI == E_Y) ? g_eps :
        (EPI == E_L1) ? g_XS : g_H1p;
    const __half* At = g_H1t;                                // DUAL only
    const __half* Bg =
        (EPI == E_T1 || EPI == E_L1) ? g_W1x :
        (EPI == E_Y) ? g_W3T : g_W2x;

    extern __shared__ __align__(16) __half smdyn[];
    __half* sAp = smdyn;                                   // [NSTG][64][72]
    __half* sAt = smdyn + NSTG * A64;                      // DUAL only
    __half* sB  = smdyn + (DUAL ? 2 : 1) * NSTG * A64;     // [NSTG][64][136]
    __shared__ float rsum[4][64];

    const int tid = threadIdx.x, lane = tid & 31, warp = tid >> 5;
    const int m0 = blockIdx.y * 64, n0 = blockIdx.x * BN;
    const int wm = (warp & 1) * 32, wn = (warp >> 1) * 32;

    float cp[2][4][4];
    float ct[DUAL ? 2 : 1][4][4];
#pragma unroll
    for (int i = 0; i < 2; i++)
#pragma unroll
        for (int j = 0; j < 4; j++)
#pragma unroll
            for (int k = 0; k < 4; k++) {
                cp[i][j][k] = 0.f;
                if (DUAL) ct[i][j][k] = 0.f;
            }

    auto pf = [&](int kt, int bufi) {
        const int k0 = kt * BK;
        __half* dAp = sAp + bufi * A64;
        __half* dB  = sB + bufi * B_STG;
#pragma unroll
        for (int i = 0; i < 2; i++) {
            int ch = tid + 256 * i;
            int r = ch >> 3, c8 = (ch & 7) * 8;
            int kg = (k0 + c8) & KMASK;
            cp16(smem_u32(dAp + r * LDA_S + c8), Ap + (size_t)(m0 + r) * LDA_G + kg);
            if (DUAL)
                cp16(smem_u32(sAt + bufi * A64 + r * LDA_S + c8),
                     At + (size_t)(m0 + r) * LDA_G + kg);
        }
#pragma unroll
        for (int i = 0; i < 4; i++) {
            int ch = tid + 256 * i;
            int r = ch >> 4, c8 = (ch & 15) * 8;
            cp16(smem_u32(dB + r * LDB_S + c8), Bg + (size_t)(k0 + r) * HH + n0 + c8);
        }
        cp_commit();
    };

    const int nk = Kd / BK;
    pf(0, 0);
    pf(1, 1);
    for (int kt = 0; kt < nk; kt++) {
        const int buf = kt % NSTG;
        if (kt == nk - 1) cp_wait0(); else cp_wait1();
        __syncthreads();
        if (kt + 2 < nk) pf(kt + 2, (kt + 2) % NSTG);

        const __half* cAp = sAp + buf * A64;
        const __half* cAt = sAt + buf * A64;
        const __half* cB  = sB + buf * B_STG;
#pragma unroll
        for (int kk = 0; kk < BK; kk += 16) {
            uint32_t a[2][4], at_[DUAL ? 2 : 1][4], b[2][4];
#pragma unroll
            for (int mf = 0; mf < 2; mf++) {
                uint32_t off = (wm + mf * 16 + (lane & 15)) * LDA_S + kk + ((lane >> 4) << 3);
                ldsm4(a[mf], smem_u32(cAp + off));
                if (DUAL) ldsm4(at_[mf], smem_u32(cAt + off));
            }
#pragma unroll
            for (int nb = 0; nb < 2; nb++)
                ldsm4t(b[nb], smem_u32(cB + (kk + (lane & 7) + ((lane >> 3) & 1) * 8) * LDB_S
                                          + wn + nb * 16 + ((lane >> 4) << 3)));
#pragma unroll
            for (int mf = 0; mf < 2; mf++)
#pragma unroll
                for (int ns = 0; ns < 4; ns++) {
                    mma16816(cp[mf][ns], a[mf], b[ns >> 1][(ns & 1) * 2],
                             b[ns >> 1][(ns & 1) * 2 + 1]);
                    if (DUAL)
                        mma16816(ct[mf][ns], at_[mf], b[ns >> 1][(ns & 1) * 2],
                                 b[ns >> 1][(ns & 1) * 2 + 1]);
                }
        }
    }

    const int g = lane >> 2, tig = lane & 3;

    if (EPI == E_L2F) {
        float tacc[2][2] = {{0.f, 0.f}, {0.f, 0.f}};
#pragma unroll
        for (int mf = 0; mf < 2; mf++)
#pragma unroll
            for (int ns = 0; ns < 4; ns++) {
                int col = n0 + wn + ns * 8 + tig * 2;
                int r0 = m0 + wm + mf * 16 + g;
#pragma unroll
                for (int half_ = 0; half_ < 2; half_++) {
                    int r = r0 + half_ * 8;
                    size_t ob = (size_t)r * HH + col;
                    float h0 = tanhf(cp[mf][ns][half_ * 2 + 0] + bias[col]);
                    float h1 = tanhf(cp[mf][ns][half_ * 2 + 1] + bias[col + 1]);
                    *(uint32_t*)(g_H2p + ob) = h2pack(h0, h1);
                    float u0 = ct[mf][ns][half_ * 2 + 0] * (1.f - h0 * h0);
                    float u1 = ct[mf][ns][half_ * 2 + 1] * (1.f - h1 * h1);
                    float y0, y1;
                    h2unpack(*(const uint32_t*)(g_Y + ob), y0, y1);
                    tacc[mf][half_] += u0 * y0 + u1 * y1;
                }
            }
#pragma unroll
        for (int mf = 0; mf < 2; mf++)
#pragma unroll
            for (int half_ = 0; half_ < 2; half_++) {
                float s = tacc[mf][half_];
                s += __shfl_xor_sync(0xffffffffu, s, 1);
                s += __shfl_xor_sync(0xffffffffu, s, 2);
                if (tig == 0) rsum[warp >> 1][wm + mf * 16 + half_ * 8 + g] = s;
            }
        __syncthreads();
        if (tid < 64) {
            float t = rsum[0][tid] + rsum[1][tid] + rsum[2][tid] + rsum[3][tid];
            g_tracep[(size_t)blockIdx.x * BB + m0 + tid] = t;
        }
        return;
    }

#pragma unroll
    for (int mf = 0; mf < 2; mf++)
#pragma unroll
        for (int ns = 0; ns < 4; ns++) {
            int col = n0 + wn + ns * 8 + tig * 2;
            int r0 = m0 + wm + mf * 16 + g;
#pragma unroll
            for (int half_ = 0; half_ < 2; half_++) {
                int r = r0 + half_ * 8;
                float v0 = cp[mf][ns][half_ * 2 + 0];
                float v1 = cp[mf][ns][half_ * 2 + 1];
                if (EPI == E_T1 || EPI == E_Y) {
                    __half* dst = (EPI == E_T1) ? g_T1 : g_Y;
                    size_t idx = (size_t)r * HH + col;
                    *(uint32_t*)(dst + idx) = h2pack(v0, v1);
                } else {  // E_L1 (initial eval only)
                    size_t ob = (size_t)r * HH + col;
                    float h0 = tanhf(v0 + tval * w1t[col] + bias[col]);
                    float h1 = tanhf(v1 + tval * w1t[col + 1] + bias[col + 1]);
                    *(uint32_t*)(g_H1p + ob) = h2pack(h0, h1);
                    float t0, t1;
                    h2unpack(*(const uint32_t*)(g_T1 + ob), t0, t1);
                    float u0 = (1.f - h0 * h0) * t0;
                    float u1 = (1.f - h1 * h1) * t1;
                    *(uint32_t*)(g_H1t + ob) = h2pack(u0, u1);
                }
            }
        }
}

// ---------------- fused L3-primal + RK + next-eval L1 ----------------
// Phase A: dx = H2p @ W3 (split K=2048), RK update -> XS (fp16) kept in smem.
// Phase B: H1 = tanh([XS|XS] @ W1x + ...) for the NEXT eval, XS read from smem.
constexpr int LDXS = 136;   // XS smem tile [64][136]

__global__ __launch_bounds__(256, 2)
void l3l1_k(const float* __restrict__ b3, const float* __restrict__ b1,
            const float* __restrict__ w1t, float tval, float h, int st, int doL1) {
    extern __shared__ __align__(16) __half smdyn[];
    __half* sA  = smdyn;                     // phase A: [NSTG][64][72]
    __half* sB  = smdyn + NSTG * A64;        // phase A: [NSTG][64][136]
    __half* XSs = smdyn;                     // phase B: [64][136]  (8704 halves)
    __half* sBB = smdyn + 64 * LDB_S;        // phase B: [NSTG][64][136]

    const int tid = threadIdx.x, lane = tid & 31, warp = tid >> 5;
    const int m0 = blockIdx.y * 64;
    const int wm = (warp & 1) * 32, wn = (warp >> 1) * 32;
    const int g = lane >> 2, tig = lane & 3;

    float cp[2][4][4];
#pragma unroll
    for (int i = 0; i < 2; i++)
#pragma unroll
        for (int j = 0; j < 4; j++)
#pragma unroll
            for (int k = 0; k < 4; k++) cp[i][j][k] = 0.f;

    // ---- Phase A mainloop: logical K=2048 over H2p (masked) x W3x ----
    auto pfA = [&](int kt, int bufi) {
        const int k0 = kt * BK;
#pragma unroll
        for (int i = 0; i < 2; i++) {
            int ch = tid + 256 * i;
            int r = ch >> 3, c8 = (ch & 7) * 8;
            int kg = (k0 + c8) & (HH - 1);
            cp16(smem_u32(sA + bufi * A64 + r * LDA_S + c8),
                 g_H2p + (size_t)(m0 + r) * HH + kg);
        }
#pragma unroll
        for (int i = 0; i < 4; i++) {
            int ch = tid + 256 * i;
            int r = ch >> 4, c8 = (ch & 15) * 8;
            cp16(smem_u32(sB + bufi * B_STG + r * LDB_S + c8),
                 g_W3x + (size_t)(k0 + r) * FF + c8);
        }
        cp_commit();
    };

    pfA(0, 0);
    pfA(1, 1);
    const int nkA = 2048 / BK;   // 32
    for (int kt = 0; kt < nkA; kt++) {
        const int buf = kt % NSTG;
        if (kt == nkA - 1) cp_wait0(); else cp_wait1();
        __syncthreads();
        if (kt + 2 < nkA) pfA(kt + 2, (kt + 2) % NSTG);

        const __half* cA = sA + buf * A64;
        const __half* cB = sB + buf * B_STG;
#pragma unroll
        for (int kk = 0; kk < BK; kk += 16) {
            uint32_t a[2][4], b[2][4];
#pragma unroll
            for (int mf = 0; mf < 2; mf++)
                ldsm4(a[mf], smem_u32(cA + (wm + mf * 16 + (lane & 15)) * LDA_S
                                         + kk + ((lane >> 4) << 3)));
#pragma unroll
            for (int nb = 0; nb < 2; nb++)
                ldsm4t(b[nb], smem_u32(cB + (kk + (lane & 7) + ((lane >> 3) & 1) * 8) * LDB_S
                                          + wn + nb * 16 + ((lane >> 4) << 3)));
#pragma unroll
            for (int mf = 0; mf < 2; mf++)
#pragma unroll
                for (int ns = 0; ns < 4; ns++)
                    mma16816(cp[mf][ns], a[mf], b[ns >> 1][(ns & 1) * 2],
                             b[ns >> 1][(ns & 1) * 2 + 1]);
        }
    }
    __syncthreads();   // done reading phase-A tiles; smem may be overwritten

    // ---- Phase A epilogue: logdet + RK update, XS into smem ----
    if (tid < 64) {
        int row = m0 + tid;
        float tr = 0.f;
#pragma unroll
        for (int cix = 0; cix < 8; cix++) tr += g_tracep[(size_t)cix * BB + row];
        if (st == 0)      g_accL[row] = tr;
        else if (st < 3)  g_accL[row] += 2.f * tr;
        else              g_logdet[row] -= (h / 6.f) * (g_accL[row] + tr);
    }
#pragma unroll
    for (int mf = 0; mf < 2; mf++)
#pragma unroll
        for (int ns = 0; ns < 4; ns++) {
            int col = wn + ns * 8 + tig * 2;
            int r0 = m0 + wm + mf * 16 + g;
#pragma unroll
            for (int half_ = 0; half_ < 2; half_++) {
                int r = r0 + half_ * 8;
                __half hx[2];
#pragma unroll
                for (int j = 0; j < 2; j++) {
                    float k = cp[mf][ns][half_ * 2 + j] + b3[col + j];
                    size_t i = (size_t)r * FF + col + j;
                    float xc = g_xcur[i];
                    float xs;
                    if (st == 0)      { g_accX[i] = k;         xs = xc + 0.5f * h * k; }
                    else if (st == 1) { g_accX[i] += 2.f * k;  xs = xc + 0.5f * h * k; }
                    else if (st == 2) { g_accX[i] += 2.f * k;  xs = xc + h * k; }
                    else {
                        float xn = xc + (h / 6.f) * (g_accX[i] + k);
                        g_xcur[i] = xn;
                        xs = xn;
                    }
                    hx[j] = __float2half(xs);
                }
                *(__half2*)(XSs + (size_t)(wm + mf * 16 + half_ * 8 + g) * LDXS + col) =
                    *reinterpret_cast<__half2*>(hx);
            }
        }
    __syncthreads();
    if (!doL1) return;

    // ---- Phase B: H1 = tanh([XS|XS] @ W1x + t*w1t + b1) ; H1t via T1 ----
    auto pfB = [&](int tix, int bufi) {
        const int nc = tix >> 2, kt = tix & 3;
        const int k0 = kt * 64;
#pragma unroll
        for (int i = 0; i < 4; i++) {
            int ch = tid + 256 * i;
            int r = ch >> 4, c8 = (ch & 15) * 8;
            cp16(smem_u32(sBB + bufi * B_STG + r * LDB_S + c8),
                 g_W1x + (size_t)(k0 + r) * HH + nc * 128 + c8);
        }
        cp_commit();
    };

    pfB(0, 0);
    pfB(1, 1);
    for (int tix = 0; tix < 32; tix++) {
        const int buf = tix % NSTG;
        const int kt = tix & 3;
        if (tix == 31) cp_wait0(); else cp_wait1();
        __syncthreads();
        if (tix + 2 < 32) pfB(tix + 2, (tix + 2) % NSTG);

        if (kt == 0) {
#pragma unroll
            for (int i = 0; i < 2; i++)
#pragma unroll
                for (int j = 0; j < 4; j++)
#pragma unroll
                    for (int k = 0; k < 4; k++) cp[i][j][k] = 0.f;
        }
        const __half* cB = sBB + buf * B_STG;
#pragma unroll
        for (int kk = 0; kk < BK; kk += 16) {
            uint32_t a[2][4], b[2][4];
#pragma unroll
            for (int mf = 0; mf < 2; mf++)
                ldsm4(a[mf], smem_u32(XSs + (wm + mf * 16 + (lane & 15)) * LDXS
                                          + (kt & 1) * 64 + kk + ((lane >> 4) << 3)));
#pragma unroll
            for (int nb = 0; nb < 2; nb++)
                ldsm4t(b[nb], smem_u32(cB + (kk + (lane & 7) + ((lane >> 3) & 1) * 8) * LDB_S
                                          + wn + nb * 16 + ((lane >> 4) << 3)));
#pragma unroll
            for (int mf = 0; mf < 2; mf++)
#pragma unroll
                for (int ns = 0; ns < 4; ns++)
                    mma16816(cp[mf][ns], a[mf], b[ns >> 1][(ns & 1) * 2],
                             b[ns >> 1][(ns & 1) * 2 + 1]);
        }

        if (kt == 3) {   // epilogue for this N-chunk
            const int nc = tix >> 2;
#pragma unroll
            for (int mf = 0; mf < 2; mf++)
#pragma unroll
                for (int ns = 0; ns < 4; ns++) {
                    int col = nc * 128 + wn + ns * 8 + tig * 2;
                    int r0 = m0 + wm + mf * 16 + g;
#pragma unroll
                    for (int half_ = 0; half_ < 2; half_++) {
                        int r = r0 + half_ * 8;
                        size_t ob = (size_t)r * HH + col;
                        float v0 = cp[mf][ns][half_ * 2 + 0];
                        float v1 = cp[mf][ns][half_ * 2 + 1];
                        float h0 = tanhf(v0 + tval * w1t[col] + b1[col]);
                        float h1 = tanhf(v1 + tval * w1t[col + 1] + b1[col + 1]);
                        *(uint32_t*)(g_H1p + ob) = h2pack(h0, h1);
                        float t0, t1;
                        h2unpack(*(const uint32_t*)(g_T1 + ob), t0, t1);
                        float u0 = (1.f - h0 * h0) * t0;
                        float u1 = (1.f - h1 * h1) * t1;
                        *(uint32_t*)(g_H1t + ob) = h2pack(u0, u1);
                    }
                }
        }
    }
}

// ---------------- setup / output ----------------
__global__ void setup_k(const float* __restrict__ x, const float* __restrict__ eps,
                        const float* __restrict__ W1, const float* __restrict__ W2,
                        const float* __restrict__ W3) {
    int i = blockIdx.x * blockDim.x + threadIdx.x;
    if (i < BB * FF) {
        float v = x[i];
        g_xcur[i] = v;
        g_XS[i]  = __float2half(v);
        g_eps[i] = __float2half(eps[i]);   // +-1 exact
    }
    if (i < BB) g_logdet[i] = 0.f;
    if (i < FF * HH) {                 // W1 rows 0..127 -> [256][1024] hi;lo
        int k = i / HH, n = i % HH;
        float w = W1[i];
        __half wh = __float2half(w);
        __half wl = __float2half(w - __half2float(wh));
        g_W1x[(size_t)k * HH + n]        = wh;
        g_W1x[(size_t)(k + FF) * HH + n] = wl;
    }
    if (i < HH * HH) {                 // W2 hi only
        g_W2x[i] = __float2half(W2[i]);
    }
    if (i < HH * FF) {                 // W3 [1024][128]
        int r3 = i / FF, c3 = i % FF;
        float w = W3[i];
        __half wh = __float2half(w);
        __half wl = __float2half(w - __half2float(wh));
        g_W3x[(size_t)r3 * FF + c3]          = wh;
        g_W3x[(size_t)(r3 + HH) * FF + c3]   = wl;
        g_W3T[(size_t)c3 * HH + r3]          = wh;
        g_W3T[(size_t)(c3 + FF) * HH + r3]   = wl;
    }
}

__global__ void finish_k(float* __restrict__ out) {
    int i = blockIdx.x * blockDim.x + threadIdx.x;
    if (i < BB * FF) out[i] = g_xcur[i];
    if (i < BB) out[BB * FF + i] = g_logdet[i];
}

// ---------------- launch ----------------
extern "C" void kernel_launch(void* const* d_in, const int* in_sizes, int n_in,
                              void* d_out, int out_size) {
    const float* x   = (const float*)d_in[0];
    const float* eps = (const float*)d_in[1];
    const float* W1  = (const float*)d_in[2];
    const float* b1  = (const float*)d_in[3];
    const float* W2  = (const float*)d_in[4];
    const float* b2  = (const float*)d_in[5];
    const float* W3  = (const float*)d_in[6];
    const float* b3  = (const float*)d_in[7];
    float* out = (float*)d_out;

    static bool attr_done = false;
    if (!attr_done) {
        cudaFuncSetAttribute(gemm_k<E_T1>,  cudaFuncAttributeMaxDynamicSharedMemorySize, SM_SINGLE);
        cudaFuncSetAttribute(gemm_k<E_Y>,   cudaFuncAttributeMaxDynamicSharedMemorySize, SM_SINGLE);
        cudaFuncSetAttribute(gemm_k<E_L1>,  cudaFuncAttributeMaxDynamicSharedMemorySize, SM_SINGLE);
        cudaFuncSetAttribute(gemm_k<E_L2F>, cudaFuncAttributeMaxDynamicSharedMemorySize, SM_DUAL);
        cudaFuncSetAttribute(l3l1_k,        cudaFuncAttributeMaxDynamicSharedMemorySize, SM_SINGLE);
        attr_done = true;
    }

    const int ew = (BB * FF + 255) / 256;
    setup_k<<<ew, 256>>>(x, eps, W1, W2, W3);

    const float h = 1.0f / NSTEPS;
    const float stc[4] = {0.f, 0.5f, 0.5f, 1.f};
    const float* w1t = W1 + FF * HH;   // W1 row 128 (time column), fp32

    // Constants: T1 = eps @ W1, Y = eps @ W3^T
    gemm_k<E_T1><<<dim3(8, BB / 64), 256, SM_SINGLE>>>(nullptr, nullptr, 0.f, h, 0);
    gemm_k<E_Y> <<<dim3(8, BB / 64), 256, SM_SINGLE>>>(nullptr, nullptr, 0.f, h, 0);

    // Initial L1 (eval 0, t = 0)
    gemm_k<E_L1><<<dim3(8, BB / 64), 256, SM_SINGLE>>>(b1, w1t, 0.f, h, 0);

    const int NEV = NSTEPS * 4;
    for (int ev = 0; ev < NEV; ev++) {
        int st = ev & 3;
        gemm_k<E_L2F><<<dim3(8, BB / 64), 256, SM_DUAL>>>(b2, nullptr, 0.f, h, st);
        int nxt = ev + 1;
        float tv_next = (nxt < NEV) ? ((nxt / 4) * h + stc[nxt & 3] * h) : 0.f;
        l3l1_k<<<dim3(1, BB / 64), 256, SM_SINGLE>>>(b3, b1, w1t, tv_next, h, st,
                                                     (nxt < NEV) ? 1 : 0);
    }
    finish_k<<<ew, 256>>>(out);
}

// round 14
// speedup vs baseline: 1.1027x; 1.0994x over previous
#include <cuda_runtime.h>
#include <cuda_fp16.h>
#include <cstdint>

// Problem dims
#define BB 16384
#define FF 128
#define HH 1024
#define NSTEPS 6

// ---------------- scratch (static __device__, no allocation) ----------------
// Weights [K][N] row-major
__device__ __align__(16) __half g_W1x[256 * HH];           // [256][1024] hi;lo (T1 only)
__device__ __align__(16) __half g_W1h[128 * HH];           // [128][1024] hi (per-stage L1)
__device__ __align__(16) __half g_W2x[(size_t)HH * HH];    // [1024][1024] hi only
__device__ __align__(16) __half g_W3h[(size_t)HH * FF];    // [1024][128] hi (per-stage L3)
__device__ __align__(16) __half g_W3T[256 * HH];           // [256][1024] hi;lo of W3^T (Y only)
// Activations, single copies
__device__ __align__(16) __half g_eps[(size_t)BB * FF];
__device__ __align__(16) __half g_XS [(size_t)BB * FF];
__device__ __align__(16) __half g_H1p[(size_t)BB * HH];
__device__ __align__(16) __half g_H1t[(size_t)BB * HH];
__device__ __align__(16) __half g_H2p[(size_t)BB * HH];
// constants for the tangent path, fp16
__device__ __align__(16) __half g_T1[(size_t)BB * HH];     // eps @ W1 (exact weights)
__device__ __align__(16) __half g_Y [(size_t)BB * HH];     // eps @ W3^T (exact weights)
// fp32 state
__device__ float g_tracep[(size_t)8 * BB]; // per-n-CTA trace partials (deterministic)
__device__ float g_xcur[BB * FF];
__device__ float g_accX[BB * FF];
__device__ float g_accL[BB];
__device__ float g_logdet[BB];

// ---------------- helpers ----------------
__device__ __forceinline__ uint32_t smem_u32(const void* p) {
    return (uint32_t)__cvta_generic_to_shared(p);
}
__device__ __forceinline__ void cp16(uint32_t s, const void* g) {
    asm volatile("cp.async.cg.shared.global [%0], [%1], 16;\n" :: "r"(s), "l"(g));
}
__device__ __forceinline__ void cp_commit() { asm volatile("cp.async.commit_group;\n"); }
__device__ __forceinline__ void cp_wait0()  { asm volatile("cp.async.wait_group 0;\n"); }
__device__ __forceinline__ void cp_wait1()  { asm volatile("cp.async.wait_group 1;\n"); }

__device__ __forceinline__ void ldsm4(uint32_t* r, uint32_t a) {
    asm volatile("ldmatrix.sync.aligned.m8n8.x4.shared.b16 {%0,%1,%2,%3},[%4];"
                 : "=r"(r[0]), "=r"(r[1]), "=r"(r[2]), "=r"(r[3]) : "r"(a));
}
__device__ __forceinline__ void ldsm4t(uint32_t* r, uint32_t a) {
    asm volatile("ldmatrix.sync.aligned.m8n8.x4.trans.shared.b16 {%0,%1,%2,%3},[%4];"
                 : "=r"(r[0]), "=r"(r[1]), "=r"(r[2]), "=r"(r[3]) : "r"(a));
}
__device__ __forceinline__ void mma16816(float* c, const uint32_t* a, uint32_t b0, uint32_t b1) {
    asm volatile(
        "mma.sync.aligned.m16n8k16.row.col.f32.f16.f16.f32 "
        "{%0,%1,%2,%3},{%4,%5,%6,%7},{%8,%9},{%0,%1,%2,%3};"
        : "+f"(c[0]), "+f"(c[1]), "+f"(c[2]), "+f"(c[3])
        : "r"(a[0]), "r"(a[1]), "r"(a[2]), "r"(a[3]), "r"(b0), "r"(b1));
}
__device__ __forceinline__ uint32_t h2pack(float a, float b) {
    __half2 t = __floats2half2_rn(a, b);
    return *reinterpret_cast<uint32_t*>(&t);
}
__device__ __forceinline__ void h2unpack(uint32_t v, float& a, float& b) {
    __half2 t = *reinterpret_cast<__half2*>(&v);
    a = __half2float(__low2half(t));
    b = __half2float(__high2half(t));
}

// ---------------- kernel ids ----------------
enum { E_T1 = 0, E_Y, E_L1, E_L2F, E_L3P };

// ---------------- fused GEMM core ----------------
// BMT=64, BN=128, BK=64, 256 threads, 8 warps (2 x 4), warp tile 32x32.
constexpr int BMT = 64, BN = 128, BK = 64, NSTG = 3;
constexpr int LDA_S = BK + 8;          // 72
constexpr int LDB_S = BN + 8;          // 136
constexpr int A_STG = BMT * LDA_S;     // 4608
constexpr int B_STG = BK * LDB_S;      // 8704
constexpr int SM_SINGLE = NSTG * (A_STG + B_STG) * 2;       // 79872 B
constexpr int SM_DUAL   = NSTG * (2 * A_STG + B_STG) * 2;   // 107520 B

template <int EPI>
__global__ __launch_bounds__(256, 2)
void gemm_k(const float* __restrict__ bias, const float* __restrict__ w1t,
            float tval, float h, int st) {
    constexpr bool DUAL = (EPI == E_L2F);
    constexpr int Nd = (EPI == E_L3P) ? FF : HH;
    constexpr int Kd = (EPI == E_T1 || EPI == E_Y) ? 256 :
                       (EPI == E_L1) ? 128 : 1024;            // logical K
    constexpr int LDA_G = (EPI == E_T1 || EPI == E_Y || EPI == E_L1) ? FF : HH;
    constexpr int KMASK = LDA_G - 1;

    const __half* Ap =
        (EPI == E_T1 || EPI == E_Y) ? g_eps :
        (EPI == E_L1) ? g_XS :
        (EPI == E_L2F) ? g_H1p : g_H2p;
    const __half* At = g_H1t;                                  // DUAL only
    const __half* Bg =
        (EPI == E_T1) ? g_W1x :
        (EPI == E_Y)  ? g_W3T :
        (EPI == E_L1) ? g_W1h :
        (EPI == E_L2F) ? g_W2x : g_W3h;

    extern __shared__ __align__(16) __half smdyn[];
    __half* sAp = smdyn;                                   // [NSTG][64][72]
    __half* sAt = smdyn + NSTG * A_STG;                    // DUAL only
    __half* sB  = smdyn + (DUAL ? 2 : 1) * NSTG * A_STG;   // [NSTG][64][136]
    __shared__ float rsum[4][BMT];

    const int tid = threadIdx.x, lane = tid & 31, warp = tid >> 5;
    const int m0 = blockIdx.y * BMT, n0 = blockIdx.x * BN;
    const int wm = (warp & 1) * 32, wn = (warp >> 1) * 32;

    float cp[2][4][4];
    float ct[DUAL ? 2 : 1][4][4];
#pragma unroll
    for (int i = 0; i < 2; i++)
#pragma unroll
        for (int j = 0; j < 4; j++)
#pragma unroll
            for (int k = 0; k < 4; k++) {
                cp[i][j][k] = 0.f;
                if (DUAL) ct[i][j][k] = 0.f;
            }

    auto pf = [&](int kt, int bufi) {
        const int k0 = kt * BK;
        __half* dAp = sAp + bufi * A_STG;
        __half* dB  = sB + bufi * B_STG;
#pragma unroll
        for (int i = 0; i < 2; i++) {          // A: 512 chunks of 8 halves
            int ch = tid + 256 * i;
            int r = ch >> 3, c8 = (ch & 7) * 8;
            int kg = (k0 + c8) & KMASK;
            cp16(smem_u32(dAp + r * LDA_S + c8), Ap + (size_t)(m0 + r) * LDA_G + kg);
            if (DUAL)
                cp16(smem_u32(sAt + bufi * A_STG + r * LDA_S + c8),
                     At + (size_t)(m0 + r) * LDA_G + kg);
        }
#pragma unroll
        for (int i = 0; i < 4; i++) {          // B: 1024 chunks
            int ch = tid + 256 * i;
            int r = ch >> 4, c8 = (ch & 15) * 8;
            cp16(smem_u32(dB + r * LDB_S + c8), Bg + (size_t)(k0 + r) * Nd + n0 + c8);
        }
        cp_commit();
    };

    const int nk = Kd / BK;
    pf(0, 0);
    if (nk > 1) pf(1, 1);
    for (int kt = 0; kt < nk; kt++) {
        const int buf = kt % NSTG;
        if (kt == nk - 1) cp_wait0(); else cp_wait1();
        __syncthreads();
        if (kt + 2 < nk) pf(kt + 2, (kt + 2) % NSTG);

        const __half* cAp = sAp + buf * A_STG;
        const __half* cAt = sAt + buf * A_STG;
        const __half* cB  = sB + buf * B_STG;
#pragma unroll
        for (int kk = 0; kk < BK; kk += 16) {
            uint32_t a[2][4], at_[DUAL ? 2 : 1][4], b[2][4];
#pragma unroll
            for (int mf = 0; mf < 2; mf++) {
                uint32_t off = (wm + mf * 16 + (lane & 15)) * LDA_S + kk + ((lane >> 4) << 3);
                ldsm4(a[mf], smem_u32(cAp + off));
                if (DUAL) ldsm4(at_[mf], smem_u32(cAt + off));
            }
#pragma unroll
            for (int nb = 0; nb < 2; nb++)
                ldsm4t(b[nb], smem_u32(cB + (kk + (lane & 7) + ((lane >> 3) & 1) * 8) * LDB_S
                                          + wn + nb * 16 + ((lane >> 4) << 3)));
#pragma unroll
            for (int mf = 0; mf < 2; mf++)
#pragma unroll
                for (int ns = 0; ns < 4; ns++) {
                    mma16816(cp[mf][ns], a[mf], b[ns >> 1][(ns & 1) * 2],
                             b[ns >> 1][(ns & 1) * 2 + 1]);
                    if (DUAL)
                        mma16816(ct[mf][ns], at_[mf], b[ns >> 1][(ns & 1) * 2],
                                 b[ns >> 1][(ns & 1) * 2 + 1]);
                }
        }
    }

    // ---------------- epilogues ----------------
    const int g = lane >> 2, tig = lane & 3;

    if (EPI == E_L3P) {
        // RK logdet update from completed trace partials (written by L2F)
        if (tid < BMT) {
            int row = m0 + tid;
            float tr = 0.f;
#pragma unroll
            for (int cix = 0; cix < 8; cix++) tr += g_tracep[(size_t)cix * BB + row];
            if (st == 0)      g_accL[row] = tr;
            else if (st < 3)  g_accL[row] += 2.f * tr;
            else              g_logdet[row] -= (h / 6.f) * (g_accL[row] + tr);
        }
        // primal dx + fused RK state update
#pragma unroll
        for (int mf = 0; mf < 2; mf++)
#pragma unroll
            for (int ns = 0; ns < 4; ns++) {
                int col = wn + ns * 8 + tig * 2;
                int r0 = m0 + wm + mf * 16 + g;
#pragma unroll
                for (int half_ = 0; half_ < 2; half_++) {
                    int r = r0 + half_ * 8;
#pragma unroll
                    for (int j = 0; j < 2; j++) {
                        float k = cp[mf][ns][half_ * 2 + j] + bias[col + j];
                        size_t i = (size_t)r * FF + col + j;
                        float xc = g_xcur[i];
                        float xs;
                        if (st == 0)      { g_accX[i] = k;         xs = xc + 0.5f * h * k; }
                        else if (st == 1) { g_accX[i] += 2.f * k;  xs = xc + 0.5f * h * k; }
                        else if (st == 2) { g_accX[i] += 2.f * k;  xs = xc + h * k; }
                        else {
                            float xn = xc + (h / 6.f) * (g_accX[i] + k);
                            g_xcur[i] = xn;
                            xs = xn;
                        }
                        g_XS[i] = __float2half(xs);
                    }
                }
            }
        return;
    }

    if (EPI == E_L2F) {
        float tacc[2][2] = {{0.f, 0.f}, {0.f, 0.f}};
#pragma unroll
        for (int mf = 0; mf < 2; mf++)
#pragma unroll
            for (int ns = 0; ns < 4; ns++) {
                int col = n0 + wn + ns * 8 + tig * 2;
                int r0 = m0 + wm + mf * 16 + g;
#pragma unroll
                for (int half_ = 0; half_ < 2; half_++) {
                    int r = r0 + half_ * 8;
                    size_t ob = (size_t)r * HH + col;
                    float h0 = tanhf(cp[mf][ns][half_ * 2 + 0] + bias[col]);
                    float h1 = tanhf(cp[mf][ns][half_ * 2 + 1] + bias[col + 1]);
                    *(uint32_t*)(g_H2p + ob) = h2pack(h0, h1);
                    float u0 = ct[mf][ns][half_ * 2 + 0] * (1.f - h0 * h0);
                    float u1 = ct[mf][ns][half_ * 2 + 1] * (1.f - h1 * h1);
                    float y0, y1;
                    h2unpack(*(const uint32_t*)(g_Y + ob), y0, y1);
                    tacc[mf][half_] += u0 * y0 + u1 * y1;
                }
            }
        // deterministic trace reduction: quad-shfl -> shared -> global partial
#pragma unroll
        for (int mf = 0; mf < 2; mf++)
#pragma unroll
            for (int half_ = 0; half_ < 2; half_++) {
                float s = tacc[mf][half_];
                s += __shfl_xor_sync(0xffffffffu, s, 1);
                s += __shfl_xor_sync(0xffffffffu, s, 2);
                if (tig == 0) rsum[warp >> 1][wm + mf * 16 + half_ * 8 + g] = s;
            }
        __syncthreads();
        if (tid < BMT) {
            float t = rsum[0][tid] + rsum[1][tid] + rsum[2][tid] + rsum[3][tid];
            g_tracep[(size_t)blockIdx.x * BB + m0 + tid] = t;
        }
        return;
    }

#pragma unroll
    for (int mf = 0; mf < 2; mf++)
#pragma unroll
        for (int ns = 0; ns < 4; ns++) {
            int col = n0 + wn + ns * 8 + tig * 2;
            int r0 = m0 + wm + mf * 16 + g;
#pragma unroll
            for (int half_ = 0; half_ < 2; half_++) {
                int r = r0 + half_ * 8;
                float v0 = cp[mf][ns][half_ * 2 + 0];
                float v1 = cp[mf][ns][half_ * 2 + 1];
                if (EPI == E_T1 || EPI == E_Y) {
                    __half* dst = (EPI == E_T1) ? g_T1 : g_Y;
                    size_t idx = (size_t)r * HH + col;
                    *(uint32_t*)(dst + idx) = h2pack(v0, v1);
                } else {  // E_L1
                    size_t ob = (size_t)r * HH + col;
                    float h0 = tanhf(v0 + tval * w1t[col] + bias[col]);
                    float h1 = tanhf(v1 + tval * w1t[col + 1] + bias[col + 1]);
                    *(uint32_t*)(g_H1p + ob) = h2pack(h0, h1);
                    float t0, t1;
                    h2unpack(*(const uint32_t*)(g_T1 + ob), t0, t1);
                    float u0 = (1.f - h0 * h0) * t0;
                    float u1 = (1.f - h1 * h1) * t1;
                    *(uint32_t*)(g_H1t + ob) = h2pack(u0, u1);
                }
            }
        }
}

// ---------------- setup / output ----------------
__global__ void setup_k(const float* __restrict__ x, const float* __restrict__ eps,
                        const float* __restrict__ W1, const float* __restrict__ W2,
                        const float* __restrict__ W3) {
    int i = blockIdx.x * blockDim.x + threadIdx.x;
    if (i < BB * FF) {
        float v = x[i];
        g_xcur[i] = v;
        g_XS[i]  = __float2half(v);
        g_eps[i] = __float2half(eps[i]);   // +-1 exact
    }
    if (i < BB) g_logdet[i] = 0.f;
    if (i < FF * HH) {                 // W1 rows 0..127
        int k = i / HH, n = i % HH;
        float w = W1[i];
        __half wh = __float2half(w);
        __half wl = __float2half(w - __half2float(wh));
        g_W1x[(size_t)k * HH + n]        = wh;    // exact split (T1)
        g_W1x[(size_t)(k + FF) * HH + n] = wl;
        g_W1h[(size_t)k * HH + n]        = wh;    // hi-only (per-stage L1)
    }
    if (i < HH * HH) {                 // W2 hi only
        g_W2x[i] = __float2half(W2[i]);
    }
    if (i < HH * FF) {                 // W3 [1024][128]
        int r3 = i / FF, c3 = i % FF;
        float w = W3[i];
        __half wh = __float2half(w);
        __half wl = __float2half(w - __half2float(wh));
        g_W3h[(size_t)r3 * FF + c3]          = wh;   // hi-only (per-stage L3)
        g_W3T[(size_t)c3 * HH + r3]          = wh;   // exact split (Y)
        g_W3T[(size_t)(c3 + FF) * HH + r3]   = wl;
    }
}

__global__ void finish_k(float* __restrict__ out) {
    int i = blockIdx.x * blockDim.x + threadIdx.x;
    if (i < BB * FF) out[i] = g_xcur[i];
    if (i < BB) out[BB * FF + i] = g_logdet[i];
}

// ---------------- launch ----------------
extern "C" void kernel_launch(void* const* d_in, const int* in_sizes, int n_in,
                              void* d_out, int out_size) {
    const float* x   = (const float*)d_in[0];
    const float* eps = (const float*)d_in[1];
    const float* W1  = (const float*)d_in[2];
    const float* b1  = (const float*)d_in[3];
    const float* W2  = (const float*)d_in[4];
    const float* b2  = (const float*)d_in[5];
    const float* W3  = (const float*)d_in[6];
    const float* b3  = (const float*)d_in[7];
    float* out = (float*)d_out;

    static bool attr_done = false;
    if (!attr_done) {
        cudaFuncSetAttribute(gemm_k<E_T1>,  cudaFuncAttributeMaxDynamicSharedMemorySize, SM_SINGLE);
        cudaFuncSetAttribute(gemm_k<E_Y>,   cudaFuncAttributeMaxDynamicSharedMemorySize, SM_SINGLE);
        cudaFuncSetAttribute(gemm_k<E_L1>,  cudaFuncAttributeMaxDynamicSharedMemorySize, SM_SINGLE);
        cudaFuncSetAttribute(gemm_k<E_L2F>, cudaFuncAttributeMaxDynamicSharedMemorySize, SM_DUAL);
        cudaFuncSetAttribute(gemm_k<E_L3P>, cudaFuncAttributeMaxDynamicSharedMemorySize, SM_SINGLE);
        attr_done = true;
    }

    const int ew = (BB * FF + 255) / 256;
    setup_k<<<ew, 256>>>(x, eps, W1, W2, W3);

    const float h = 1.0f / NSTEPS;
    const float stc[4] = {0.f, 0.5f, 0.5f, 1.f};
    const float* w1t = W1 + FF * HH;   // W1 row 128 (time column), fp32

    // Constants: T1 = eps @ W1, Y = eps @ W3^T (exact weights via hi;lo split)
    gemm_k<E_T1><<<dim3(8, BB / BMT), 256, SM_SINGLE>>>(nullptr, nullptr, 0.f, h, 0);
    gemm_k<E_Y> <<<dim3(8, BB / BMT), 256, SM_SINGLE>>>(nullptr, nullptr, 0.f, h, 0);

    for (int s = 0; s < NSTEPS; s++) {
        float t0 = s * h;
        for (int st = 0; st < 4; st++) {
            float tv = t0 + stc[st] * h;
            gemm_k<E_L1> <<<dim3(8, BB / BMT), 256, SM_SINGLE>>>(b1, w1t, tv, h, st);
            gemm_k<E_L2F><<<dim3(8, BB / BMT), 256, SM_DUAL>>>(b2, nullptr, 0.f, h, st);
            gemm_k<E_L3P><<<dim3(1, BB / BMT), 256, SM_SINGLE>>>(b3, nullptr, 0.f, h, st);
        }
    }
    finish_k<<<ew, 256>>>(out);
}

// round 15
// speedup vs baseline: 1.3212x; 1.1982x over previous
#include <cuda_runtime.h>
#include <cuda_fp16.h>
#include <cstdint>

// Problem dims
#define BB 16384
#define FF 128
#define HH 1024
#define NSTEPS 5

// ---------------- scratch (static __device__, no allocation) ----------------
// Weights [K][N] row-major
__device__ __align__(16) __half g_W1x[256 * HH];           // [256][1024] hi;lo (T1 only)
__device__ __align__(16) __half g_W1h[128 * HH];           // [128][1024] hi (per-stage L1)
__device__ __align__(16) __half g_W2x[(size_t)HH * HH];    // [1024][1024] hi only
__device__ __align__(16) __half g_W3h[(size_t)HH * FF];    // [1024][128] hi (per-stage L3)
__device__ __align__(16) __half g_W3T[256 * HH];           // [256][1024] hi;lo of W3^T (Y only)
// Activations, single copies
__device__ __align__(16) __half g_eps[(size_t)BB * FF];
__device__ __align__(16) __half g_XS [(size_t)BB * FF];
__device__ __align__(16) __half g_H1p[(size_t)BB * HH];
__device__ __align__(16) __half g_H1t[(size_t)BB * HH];
__device__ __align__(16) __half g_H2p[(size_t)BB * HH];
// constants for the tangent path, fp16
__device__ __align__(16) __half g_T1[(size_t)BB * HH];     // eps @ W1 (exact weights)
__device__ __align__(16) __half g_Y [(size_t)BB * HH];     // eps @ W3^T (exact weights)
// fp32 state
__device__ float g_tracep[(size_t)8 * BB]; // per-n-CTA trace partials (deterministic)
__device__ float g_xcur[BB * FF];
__device__ float g_accX[BB * FF];
__device__ float g_accL[BB];
__device__ float g_logdet[BB];

// ---------------- helpers ----------------
__device__ __forceinline__ uint32_t smem_u32(const void* p) {
    return (uint32_t)__cvta_generic_to_shared(p);
}
__device__ __forceinline__ void cp16(uint32_t s, const void* g) {
    asm volatile("cp.async.cg.shared.global [%0], [%1], 16;\n" :: "r"(s), "l"(g));
}
__device__ __forceinline__ void cp_commit() { asm volatile("cp.async.commit_group;\n"); }
__device__ __forceinline__ void cp_wait0()  { asm volatile("cp.async.wait_group 0;\n"); }
__device__ __forceinline__ void cp_wait1()  { asm volatile("cp.async.wait_group 1;\n"); }

__device__ __forceinline__ void ldsm4(uint32_t* r, uint32_t a) {
    asm volatile("ldmatrix.sync.aligned.m8n8.x4.shared.b16 {%0,%1,%2,%3},[%4];"
                 : "=r"(r[0]), "=r"(r[1]), "=r"(r[2]), "=r"(r[3]) : "r"(a));
}
__device__ __forceinline__ void ldsm4t(uint32_t* r, uint32_t a) {
    asm volatile("ldmatrix.sync.aligned.m8n8.x4.trans.shared.b16 {%0,%1,%2,%3},[%4];"
                 : "=r"(r[0]), "=r"(r[1]), "=r"(r[2]), "=r"(r[3]) : "r"(a));
}
__device__ __forceinline__ void mma16816(float* c, const uint32_t* a, uint32_t b0, uint32_t b1) {
    asm volatile(
        "mma.sync.aligned.m16n8k16.row.col.f32.f16.f16.f32 "
        "{%0,%1,%2,%3},{%4,%5,%6,%7},{%8,%9},{%0,%1,%2,%3};"
        : "+f"(c[0]), "+f"(c[1]), "+f"(c[2]), "+f"(c[3])
        : "r"(a[0]), "r"(a[1]), "r"(a[2]), "r"(a[3]), "r"(b0), "r"(b1));
}
__device__ __forceinline__ uint32_t h2pack(float a, float b) {
    __half2 t = __floats2half2_rn(a, b);
    return *reinterpret_cast<uint32_t*>(&t);
}
__device__ __forceinline__ void h2unpack(uint32_t v, float& a, float& b) {
    __half2 t = *reinterpret_cast<__half2*>(&v);
    a = __half2float(__low2half(t));
    b = __half2float(__high2half(t));
}

// ---------------- kernel ids ----------------
enum { E_T1 = 0, E_Y, E_L1, E_L2F, E_L3P };

// ---------------- fused GEMM core ----------------
// BMT=64, BN=128, BK=64, 256 threads, 8 warps (2 x 4), warp tile 32x32.
constexpr int BMT = 64, BN = 128, BK = 64, NSTG = 3;
constexpr int LDA_S = BK + 8;          // 72
constexpr int LDB_S = BN + 8;          // 136
constexpr int A_STG = BMT * LDA_S;     // 4608
constexpr int B_STG = BK * LDB_S;      // 8704
constexpr int SM_SINGLE = NSTG * (A_STG + B_STG) * 2;       // 79872 B
constexpr int SM_DUAL   = NSTG * (2 * A_STG + B_STG) * 2;   // 107520 B

template <int EPI>
__global__ __launch_bounds__(256, 2)
void gemm_k(const float* __restrict__ bias, const float* __restrict__ w1t,
            float tval, float h, int st) {
    constexpr bool DUAL = (EPI == E_L2F);
    constexpr int Nd = (EPI == E_L3P) ? FF : HH;
    constexpr int Kd = (EPI == E_T1 || EPI == E_Y) ? 256 :
                       (EPI == E_L1) ? 128 : 1024;            // logical K
    constexpr int LDA_G = (EPI == E_T1 || EPI == E_Y || EPI == E_L1) ? FF : HH;
    constexpr int KMASK = LDA_G - 1;

    const __half* Ap =
        (EPI == E_T1 || EPI == E_Y) ? g_eps :
        (EPI == E_L1) ? g_XS :
        (EPI == E_L2F) ? g_H1p : g_H2p;
    const __half* At = g_H1t;                                  // DUAL only
    const __half* Bg =
        (EPI == E_T1) ? g_W1x :
        (EPI == E_Y)  ? g_W3T :
        (EPI == E_L1) ? g_W1h :
        (EPI == E_L2F) ? g_W2x : g_W3h;

    extern __shared__ __align__(16) __half smdyn[];
    __half* sAp = smdyn;                                   // [NSTG][64][72]
    __half* sAt = smdyn + NSTG * A_STG;                    // DUAL only
    __half* sB  = smdyn + (DUAL ? 2 : 1) * NSTG * A_STG;   // [NSTG][64][136]
    __shared__ float rsum[4][BMT];

    const int tid = threadIdx.x, lane = tid & 31, warp = tid >> 5;
    const int m0 = blockIdx.y * BMT, n0 = blockIdx.x * BN;
    const int wm = (warp & 1) * 32, wn = (warp >> 1) * 32;

    float cp[2][4][4];
    float ct[DUAL ? 2 : 1][4][4];
#pragma unroll
    for (int i = 0; i < 2; i++)
#pragma unroll
        for (int j = 0; j < 4; j++)
#pragma unroll
            for (int k = 0; k < 4; k++) {
                cp[i][j][k] = 0.f;
                if (DUAL) ct[i][j][k] = 0.f;
            }

    auto pf = [&](int kt, int bufi) {
        const int k0 = kt * BK;
        __half* dAp = sAp + bufi * A_STG;
        __half* dB  = sB + bufi * B_STG;
#pragma unroll
        for (int i = 0; i < 2; i++) {          // A: 512 chunks of 8 halves
            int ch = tid + 256 * i;
            int r = ch >> 3, c8 = (ch & 7) * 8;
            int kg = (k0 + c8) & KMASK;
            cp16(smem_u32(dAp + r * LDA_S + c8), Ap + (size_t)(m0 + r) * LDA_G + kg);
            if (DUAL)
                cp16(smem_u32(sAt + bufi * A_STG + r * LDA_S + c8),
                     At + (size_t)(m0 + r) * LDA_G + kg);
        }
#pragma unroll
        for (int i = 0; i < 4; i++) {          // B: 1024 chunks
            int ch = tid + 256 * i;
            int r = ch >> 4, c8 = (ch & 15) * 8;
            cp16(smem_u32(dB + r * LDB_S + c8), Bg + (size_t)(k0 + r) * Nd + n0 + c8);
        }
        cp_commit();
    };

    const int nk = Kd / BK;
    pf(0, 0);
    if (nk > 1) pf(1, 1);
    for (int kt = 0; kt < nk; kt++) {
        const int buf = kt % NSTG;
        if (kt == nk - 1) cp_wait0(); else cp_wait1();
        __syncthreads();
        if (kt + 2 < nk) pf(kt + 2, (kt + 2) % NSTG);

        const __half* cAp = sAp + buf * A_STG;
        const __half* cAt = sAt + buf * A_STG;
        const __half* cB  = sB + buf * B_STG;
#pragma unroll
        for (int kk = 0; kk < BK; kk += 16) {
            uint32_t a[2][4], at_[DUAL ? 2 : 1][4], b[2][4];
#pragma unroll
            for (int mf = 0; mf < 2; mf++) {
                uint32_t off = (wm + mf * 16 + (lane & 15)) * LDA_S + kk + ((lane >> 4) << 3);
                ldsm4(a[mf], smem_u32(cAp + off));
                if (DUAL) ldsm4(at_[mf], smem_u32(cAt + off));
            }
#pragma unroll
            for (int nb = 0; nb < 2; nb++)
                ldsm4t(b[nb], smem_u32(cB + (kk + (lane & 7) + ((lane >> 3) & 1) * 8) * LDB_S
                                          + wn + nb * 16 + ((lane >> 4) << 3)));
#pragma unroll
            for (int mf = 0; mf < 2; mf++)
#pragma unroll
                for (int ns = 0; ns < 4; ns++) {
                    mma16816(cp[mf][ns], a[mf], b[ns >> 1][(ns & 1) * 2],
                             b[ns >> 1][(ns & 1) * 2 + 1]);
                    if (DUAL)
                        mma16816(ct[mf][ns], at_[mf], b[ns >> 1][(ns & 1) * 2],
                                 b[ns >> 1][(ns & 1) * 2 + 1]);
                }
        }
    }

    // ---------------- epilogues ----------------
    const int g = lane >> 2, tig = lane & 3;

    if (EPI == E_L3P) {
        // RK logdet update from completed trace partials (written by L2F)
        if (tid < BMT) {
            int row = m0 + tid;
            float tr = 0.f;
#pragma unroll
            for (int cix = 0; cix < 8; cix++) tr += g_tracep[(size_t)cix * BB + row];
            if (st == 0)      g_accL[row] = tr;
            else if (st < 3)  g_accL[row] += 2.f * tr;
            else              g_logdet[row] -= (h / 6.f) * (g_accL[row] + tr);
        }
        // primal dx + fused RK state update
#pragma unroll
        for (int mf = 0; mf < 2; mf++)
#pragma unroll
            for (int ns = 0; ns < 4; ns++) {
                int col = wn + ns * 8 + tig * 2;
                int r0 = m0 + wm + mf * 16 + g;
#pragma unroll
                for (int half_ = 0; half_ < 2; half_++) {
                    int r = r0 + half_ * 8;
#pragma unroll
                    for (int j = 0; j < 2; j++) {
                        float k = cp[mf][ns][half_ * 2 + j] + bias[col + j];
                        size_t i = (size_t)r * FF + col + j;
                        float xc = g_xcur[i];
                        float xs;
                        if (st == 0)      { g_accX[i] = k;         xs = xc + 0.5f * h * k; }
                        else if (st == 1) { g_accX[i] += 2.f * k;  xs = xc + 0.5f * h * k; }
                        else if (st == 2) { g_accX[i] += 2.f * k;  xs = xc + h * k; }
                        else {
                            float xn = xc + (h / 6.f) * (g_accX[i] + k);
                            g_xcur[i] = xn;
                            xs = xn;
                        }
                        g_XS[i] = __float2half(xs);
                    }
                }
            }
        return;
    }

    if (EPI == E_L2F) {
        float tacc[2][2] = {{0.f, 0.f}, {0.f, 0.f}};
#pragma unroll
        for (int mf = 0; mf < 2; mf++)
#pragma unroll
            for (int ns = 0; ns < 4; ns++) {
                int col = n0 + wn + ns * 8 + tig * 2;
                int r0 = m0 + wm + mf * 16 + g;
#pragma unroll
                for (int half_ = 0; half_ < 2; half_++) {
                    int r = r0 + half_ * 8;
                    size_t ob = (size_t)r * HH + col;
                    float h0 = tanhf(cp[mf][ns][half_ * 2 + 0] + bias[col]);
                    float h1 = tanhf(cp[mf][ns][half_ * 2 + 1] + bias[col + 1]);
                    *(uint32_t*)(g_H2p + ob) = h2pack(h0, h1);
                    float u0 = ct[mf][ns][half_ * 2 + 0] * (1.f - h0 * h0);
                    float u1 = ct[mf][ns][half_ * 2 + 1] * (1.f - h1 * h1);
                    float y0, y1;
                    h2unpack(*(const uint32_t*)(g_Y + ob), y0, y1);
                    tacc[mf][half_] += u0 * y0 + u1 * y1;
                }
            }
        // deterministic trace reduction: quad-shfl -> shared -> global partial
#pragma unroll
        for (int mf = 0; mf < 2; mf++)
#pragma unroll
            for (int half_ = 0; half_ < 2; half_++) {
                float s = tacc[mf][half_];
                s += __shfl_xor_sync(0xffffffffu, s, 1);
                s += __shfl_xor_sync(0xffffffffu, s, 2);
                if (tig == 0) rsum[warp >> 1][wm + mf * 16 + half_ * 8 + g] = s;
            }
        __syncthreads();
        if (tid < BMT) {
            float t = rsum[0][tid] + rsum[1][tid] + rsum[2][tid] + rsum[3][tid];
            g_tracep[(size_t)blockIdx.x * BB + m0 + tid] = t;
        }
        return;
    }

#pragma unroll
    for (int mf = 0; mf < 2; mf++)
#pragma unroll
        for (int ns = 0; ns < 4; ns++) {
            int col = n0 + wn + ns * 8 + tig * 2;
            int r0 = m0 + wm + mf * 16 + g;
#pragma unroll
            for (int half_ = 0; half_ < 2; half_++) {
                int r = r0 + half_ * 8;
                float v0 = cp[mf][ns][half_ * 2 + 0];
                float v1 = cp[mf][ns][half_ * 2 + 1];
                if (EPI == E_T1 || EPI == E_Y) {
                    __half* dst = (EPI == E_T1) ? g_T1 : g_Y;
                    size_t idx = (size_t)r * HH + col;
                    *(uint32_t*)(dst + idx) = h2pack(v0, v1);
                } else {  // E_L1
                    size_t ob = (size_t)r * HH + col;
                    float h0 = tanhf(v0 + tval * w1t[col] + bias[col]);
                    float h1 = tanhf(v1 + tval * w1t[col + 1] + bias[col + 1]);
                    *(uint32_t*)(g_H1p + ob) = h2pack(h0, h1);
                    float t0, t1;
                    h2unpack(*(const uint32_t*)(g_T1 + ob), t0, t1);
                    float u0 = (1.f - h0 * h0) * t0;
                    float u1 = (1.f - h1 * h1) * t1;
                    *(uint32_t*)(g_H1t + ob) = h2pack(u0, u1);
                }
            }
        }
}

// ---------------- setup / output ----------------
__global__ void setup_k(const float* __restrict__ x, const float* __restrict__ eps,
                        const float* __restrict__ W1, const float* __restrict__ W2,
                        const float* __restrict__ W3) {
    int i = blockIdx.x * blockDim.x + threadIdx.x;
    if (i < BB * FF) {
        float v = x[i];
        g_xcur[i] = v;
        g_XS[i]  = __float2half(v);
        g_eps[i] = __float2half(eps[i]);   // +-1 exact
    }
    if (i < BB) g_logdet[i] = 0.f;
    if (i < FF * HH) {                 // W1 rows 0..127
        int k = i / HH, n = i % HH;
        float w = W1[i];
        __half wh = __float2half(w);
        __half wl = __float2half(w - __half2float(wh));
        g_W1x[(size_t)k * HH + n]        = wh;    // exact split (T1)
        g_W1x[(size_t)(k + FF) * HH + n] = wl;
        g_W1h[(size_t)k * HH + n]        = wh;    // hi-only (per-stage L1)
    }
    if (i < HH * HH) {                 // W2 hi only
        g_W2x[i] = __float2half(W2[i]);
    }
    if (i < HH * FF) {                 // W3 [1024][128]
        int r3 = i / FF, c3 = i % FF;
        float w = W3[i];
        __half wh = __float2half(w);
        __half wl = __float2half(w - __half2float(wh));
        g_W3h[(size_t)r3 * FF + c3]          = wh;   // hi-only (per-stage L3)
        g_W3T[(size_t)c3 * HH + r3]          = wh;   // exact split (Y)
        g_W3T[(size_t)(c3 + FF) * HH + r3]   = wl;
    }
}

__global__ void finish_k(float* __restrict__ out) {
    int i = blockIdx.x * blockDim.x + threadIdx.x;
    if (i < BB * FF) out[i] = g_xcur[i];
    if (i < BB) out[BB * FF + i] = g_logdet[i];
}

// ---------------- launch ----------------
extern "C" void kernel_launch(void* const* d_in, const int* in_sizes, int n_in,
                              void* d_out, int out_size) {
    const float* x   = (const float*)d_in[0];
    const float* eps = (const float*)d_in[1];
    const float* W1  = (const float*)d_in[2];
    const float* b1  = (const float*)d_in[3];
    const float* W2  = (const float*)d_in[4];
    const float* b2  = (const float*)d_in[5];
    const float* W3  = (const float*)d_in[6];
    const float* b3  = (const float*)d_in[7];
    float* out = (float*)d_out;

    static bool attr_done = false;
    if (!attr_done) {
        cudaFuncSetAttribute(gemm_k<E_T1>,  cudaFuncAttributeMaxDynamicSharedMemorySize, SM_SINGLE);
        cudaFuncSetAttribute(gemm_k<E_Y>,   cudaFuncAttributeMaxDynamicSharedMemorySize, SM_SINGLE);
        cudaFuncSetAttribute(gemm_k<E_L1>,  cudaFuncAttributeMaxDynamicSharedMemorySize, SM_SINGLE);
        cudaFuncSetAttribute(gemm_k<E_L2F>, cudaFuncAttributeMaxDynamicSharedMemorySize, SM_DUAL);
        cudaFuncSetAttribute(gemm_k<E_L3P>, cudaFuncAttributeMaxDynamicSharedMemorySize, SM_SINGLE);
        attr_done = true;
    }

    const int ew = (BB * FF + 255) / 256;
    setup_k<<<ew, 256>>>(x, eps, W1, W2, W3);

    const float h = 1.0f / NSTEPS;
    const float stc[4] = {0.f, 0.5f, 0.5f, 1.f};
    const float* w1t = W1 + FF * HH;   // W1 row 128 (time column), fp32

    // Constants: T1 = eps @ W1, Y = eps @ W3^T (exact weights via hi;lo split)
    gemm_k<E_T1><<<dim3(8, BB / BMT), 256, SM_SINGLE>>>(nullptr, nullptr, 0.f, h, 0);
    gemm_k<E_Y> <<<dim3(8, BB / BMT), 256, SM_SINGLE>>>(nullptr, nullptr, 0.f, h, 0);

    for (int s = 0; s < NSTEPS; s++) {
        float t0 = s * h;
        for (int st = 0; st < 4; st++) {
            float tv = t0 + stc[st] * h;
            gemm_k<E_L1> <<<dim3(8, BB / BMT), 256, SM_SINGLE>>>(b1, w1t, tv, h, st);
            gemm_k<E_L2F><<<dim3(8, BB / BMT), 256, SM_DUAL>>>(b2, nullptr, 0.f, h, st);
            gemm_k<E_L3P><<<dim3(1, BB / BMT), 256, SM_SINGLE>>>(b3, nullptr, 0.f, h, st);
        }
    }
    finish_k<<<ew, 256>>>(out);
}

// round 16
// speedup vs baseline: 2.1695x; 1.6420x over previous
#include <cuda_runtime.h>
#include <cuda_fp16.h>
#include <cstdint>

// Problem dims
#define BB 16384
#define FF 128
#define HH 1024
#define NSTEPS 3

// ---------------- scratch (static __device__, no allocation) ----------------
// Weights [K][N] row-major
__device__ __align__(16) __half g_W1x[256 * HH];           // [256][1024] hi;lo (T1 only)
__device__ __align__(16) __half g_W1h[128 * HH];           // [128][1024] hi (per-stage L1)
__device__ __align__(16) __half g_W2x[(size_t)HH * HH];    // [1024][1024] hi only
__device__ __align__(16) __half g_W3h[(size_t)HH * FF];    // [1024][128] hi (per-stage L3)
__device__ __align__(16) __half g_W3T[256 * HH];           // [256][1024] hi;lo of W3^T (Y only)
// Activations, single copies
__device__ __align__(16) __half g_eps[(size_t)BB * FF];
__device__ __align__(16) __half g_XS [(size_t)BB * FF];
__device__ __align__(16) __half g_H1p[(size_t)BB * HH];
__device__ __align__(16) __half g_H1t[(size_t)BB * HH];
__device__ __align__(16) __half g_H2p[(size_t)BB * HH];
// constants for the tangent path, fp16
__device__ __align__(16) __half g_T1[(size_t)BB * HH];     // eps @ W1 (exact weights)
__device__ __align__(16) __half g_Y [(size_t)BB * HH];     // eps @ W3^T (exact weights)
// fp32 state
__device__ float g_tracep[(size_t)8 * BB]; // per-n-CTA trace partials (deterministic)
__device__ float g_xcur[BB * FF];
__device__ float g_accX[BB * FF];
__device__ float g_accL[BB];
__device__ float g_logdet[BB];

// ---------------- helpers ----------------
__device__ __forceinline__ uint32_t smem_u32(const void* p) {
    return (uint32_t)__cvta_generic_to_shared(p);
}
__device__ __forceinline__ void cp16(uint32_t s, const void* g) {
    asm volatile("cp.async.cg.shared.global [%0], [%1], 16;\n" :: "r"(s), "l"(g));
}
__device__ __forceinline__ void cp_commit() { asm volatile("cp.async.commit_group;\n"); }
__device__ __forceinline__ void cp_wait0()  { asm volatile("cp.async.wait_group 0;\n"); }
__device__ __forceinline__ void cp_wait1()  { asm volatile("cp.async.wait_group 1;\n"); }

__device__ __forceinline__ void ldsm4(uint32_t* r, uint32_t a) {
    asm volatile("ldmatrix.sync.aligned.m8n8.x4.shared.b16 {%0,%1,%2,%3},[%4];"
                 : "=r"(r[0]), "=r"(r[1]), "=r"(r[2]), "=r"(r[3]) : "r"(a));
}
__device__ __forceinline__ void ldsm4t(uint32_t* r, uint32_t a) {
    asm volatile("ldmatrix.sync.aligned.m8n8.x4.trans.shared.b16 {%0,%1,%2,%3},[%4];"
                 : "=r"(r[0]), "=r"(r[1]), "=r"(r[2]), "=r"(r[3]) : "r"(a));
}
__device__ __forceinline__ void mma16816(float* c, const uint32_t* a, uint32_t b0, uint32_t b1) {
    asm volatile(
        "mma.sync.aligned.m16n8k16.row.col.f32.f16.f16.f32 "
        "{%0,%1,%2,%3},{%4,%5,%6,%7},{%8,%9},{%0,%1,%2,%3};"
        : "+f"(c[0]), "+f"(c[1]), "+f"(c[2]), "+f"(c[3])
        : "r"(a[0]), "r"(a[1]), "r"(a[2]), "r"(a[3]), "r"(b0), "r"(b1));
}
__device__ __forceinline__ uint32_t h2pack(float a, float b) {
    __half2 t = __floats2half2_rn(a, b);
    return *reinterpret_cast<uint32_t*>(&t);
}
__device__ __forceinline__ void h2unpack(uint32_t v, float& a, float& b) {
    __half2 t = *reinterpret_cast<__half2*>(&v);
    a = __half2float(__low2half(t));
    b = __half2float(__high2half(t));
}

// ---------------- kernel ids ----------------
enum { E_T1 = 0, E_Y, E_L1, E_L2F, E_L3P };

// ---------------- fused GEMM core ----------------
// BMT=64, BN=128, BK=64, 256 threads, 8 warps (2 x 4), warp tile 32x32.
constexpr int BMT = 64, BN = 128, BK = 64, NSTG = 3;
constexpr int LDA_S = BK + 8;          // 72
constexpr int LDB_S = BN + 8;          // 136
constexpr int A_STG = BMT * LDA_S;     // 4608
constexpr int B_STG = BK * LDB_S;      // 8704
constexpr int SM_SINGLE = NSTG * (A_STG + B_STG) * 2;       // 79872 B
constexpr int SM_DUAL   = NSTG * (2 * A_STG + B_STG) * 2;   // 107520 B

template <int EPI>
__global__ __launch_bounds__(256, 2)
void gemm_k(const float* __restrict__ bias, const float* __restrict__ w1t,
            float tval, float h, int st) {
    constexpr bool DUAL = (EPI == E_L2F);
    constexpr int Nd = (EPI == E_L3P) ? FF : HH;
    constexpr int Kd = (EPI == E_T1 || EPI == E_Y) ? 256 :
                       (EPI == E_L1) ? 128 : 1024;            // logical K
    constexpr int LDA_G = (EPI == E_T1 || EPI == E_Y || EPI == E_L1) ? FF : HH;
    constexpr int KMASK = LDA_G - 1;

    const __half* Ap =
        (EPI == E_T1 || EPI == E_Y) ? g_eps :
        (EPI == E_L1) ? g_XS :
        (EPI == E_L2F) ? g_H1p : g_H2p;
    const __half* At = g_H1t;                                  // DUAL only
    const __half* Bg =
        (EPI == E_T1) ? g_W1x :
        (EPI == E_Y)  ? g_W3T :
        (EPI == E_L1) ? g_W1h :
        (EPI == E_L2F) ? g_W2x : g_W3h;

    extern __shared__ __align__(16) __half smdyn[];
    __half* sAp = smdyn;                                   // [NSTG][64][72]
    __half* sAt = smdyn + NSTG * A_STG;                    // DUAL only
    __half* sB  = smdyn + (DUAL ? 2 : 1) * NSTG * A_STG;   // [NSTG][64][136]
    __shared__ float rsum[4][BMT];

    const int tid = threadIdx.x, lane = tid & 31, warp = tid >> 5;
    const int m0 = blockIdx.y * BMT, n0 = blockIdx.x * BN;
    const int wm = (warp & 1) * 32, wn = (warp >> 1) * 32;

    float cp[2][4][4];
    float ct[DUAL ? 2 : 1][4][4];
#pragma unroll
    for (int i = 0; i < 2; i++)
#pragma unroll
        for (int j = 0; j < 4; j++)
#pragma unroll
            for (int k = 0; k < 4; k++) {
                cp[i][j][k] = 0.f;
                if (DUAL) ct[i][j][k] = 0.f;
            }

    auto pf = [&](int kt, int bufi) {
        const int k0 = kt * BK;
        __half* dAp = sAp + bufi * A_STG;
        __half* dB  = sB + bufi * B_STG;
#pragma unroll
        for (int i = 0; i < 2; i++) {          // A: 512 chunks of 8 halves
            int ch = tid + 256 * i;
            int r = ch >> 3, c8 = (ch & 7) * 8;
            int kg = (k0 + c8) & KMASK;
            cp16(smem_u32(dAp + r * LDA_S + c8), Ap + (size_t)(m0 + r) * LDA_G + kg);
            if (DUAL)
                cp16(smem_u32(sAt + bufi * A_STG + r * LDA_S + c8),
                     At + (size_t)(m0 + r) * LDA_G + kg);
        }
#pragma unroll
        for (int i = 0; i < 4; i++) {          // B: 1024 chunks
            int ch = tid + 256 * i;
            int r = ch >> 4, c8 = (ch & 15) * 8;
            cp16(smem_u32(dB + r * LDB_S + c8), Bg + (size_t)(k0 + r) * Nd + n0 + c8);
        }
        cp_commit();
    };

    const int nk = Kd / BK;
    pf(0, 0);
    if (nk > 1) pf(1, 1);
    for (int kt = 0; kt < nk; kt++) {
        const int buf = kt % NSTG;
        if (kt == nk - 1) cp_wait0(); else cp_wait1();
        __syncthreads();
        if (kt + 2 < nk) pf(kt + 2, (kt + 2) % NSTG);

        const __half* cAp = sAp + buf * A_STG;
        const __half* cAt = sAt + buf * A_STG;
        const __half* cB  = sB + buf * B_STG;
#pragma unroll
        for (int kk = 0; kk < BK; kk += 16) {
            uint32_t a[2][4], at_[DUAL ? 2 : 1][4], b[2][4];
#pragma unroll
            for (int mf = 0; mf < 2; mf++) {
                uint32_t off = (wm + mf * 16 + (lane & 15)) * LDA_S + kk + ((lane >> 4) << 3);
                ldsm4(a[mf], smem_u32(cAp + off));
                if (DUAL) ldsm4(at_[mf], smem_u32(cAt + off));
            }
#pragma unroll
            for (int nb = 0; nb < 2; nb++)
                ldsm4t(b[nb], smem_u32(cB + (kk + (lane & 7) + ((lane >> 3) & 1) * 8) * LDB_S
                                          + wn + nb * 16 + ((lane >> 4) << 3)));
#pragma unroll
            for (int mf = 0; mf < 2; mf++)
#pragma unroll
                for (int ns = 0; ns < 4; ns++) {
                    mma16816(cp[mf][ns], a[mf], b[ns >> 1][(ns & 1) * 2],
                             b[ns >> 1][(ns & 1) * 2 + 1]);
                    if (DUAL)
                        mma16816(ct[mf][ns], at_[mf], b[ns >> 1][(ns & 1) * 2],
                                 b[ns >> 1][(ns & 1) * 2 + 1]);
                }
        }
    }

    // ---------------- epilogues ----------------
    const int g = lane >> 2, tig = lane & 3;

    if (EPI == E_L3P) {
        // RK logdet update from completed trace partials (written by L2F)
        if (tid < BMT) {
            int row = m0 + tid;
            float tr = 0.f;
#pragma unroll
            for (int cix = 0; cix < 8; cix++) tr += g_tracep[(size_t)cix * BB + row];
            if (st == 0)      g_accL[row] = tr;
            else if (st < 3)  g_accL[row] += 2.f * tr;
            else              g_logdet[row] -= (h / 6.f) * (g_accL[row] + tr);
        }
        // primal dx + fused RK state update
#pragma unroll
        for (int mf = 0; mf < 2; mf++)
#pragma unroll
            for (int ns = 0; ns < 4; ns++) {
                int col = wn + ns * 8 + tig * 2;
                int r0 = m0 + wm + mf * 16 + g;
#pragma unroll
                for (int half_ = 0; half_ < 2; half_++) {
                    int r = r0 + half_ * 8;
#pragma unroll
                    for (int j = 0; j < 2; j++) {
                        float k = cp[mf][ns][half_ * 2 + j] + bias[col + j];
                        size_t i = (size_t)r * FF + col + j;
                        float xc = g_xcur[i];
                        float xs;
                        if (st == 0)      { g_accX[i] = k;         xs = xc + 0.5f * h * k; }
                        else if (st == 1) { g_accX[i] += 2.f * k;  xs = xc + 0.5f * h * k; }
                        else if (st == 2) { g_accX[i] += 2.f * k;  xs = xc + h * k; }
                        else {
                            float xn = xc + (h / 6.f) * (g_accX[i] + k);
                            g_xcur[i] = xn;
                            xs = xn;
                        }
                        g_XS[i] = __float2half(xs);
                    }
                }
            }
        return;
    }

    if (EPI == E_L2F) {
        float tacc[2][2] = {{0.f, 0.f}, {0.f, 0.f}};
#pragma unroll
        for (int mf = 0; mf < 2; mf++)
#pragma unroll
            for (int ns = 0; ns < 4; ns++) {
                int col = n0 + wn + ns * 8 + tig * 2;
                int r0 = m0 + wm + mf * 16 + g;
#pragma unroll
                for (int half_ = 0; half_ < 2; half_++) {
                    int r = r0 + half_ * 8;
                    size_t ob = (size_t)r * HH + col;
                    float h0 = tanhf(cp[mf][ns][half_ * 2 + 0] + bias[col]);
                    float h1 = tanhf(cp[mf][ns][half_ * 2 + 1] + bias[col + 1]);
                    *(uint32_t*)(g_H2p + ob) = h2pack(h0, h1);
                    float u0 = ct[mf][ns][half_ * 2 + 0] * (1.f - h0 * h0);
                    float u1 = ct[mf][ns][half_ * 2 + 1] * (1.f - h1 * h1);
                    float y0, y1;
                    h2unpack(*(const uint32_t*)(g_Y + ob), y0, y1);
                    tacc[mf][half_] += u0 * y0 + u1 * y1;
                }
            }
        // deterministic trace reduction: quad-shfl -> shared -> global partial
#pragma unroll
        for (int mf = 0; mf < 2; mf++)
#pragma unroll
            for (int half_ = 0; half_ < 2; half_++) {
                float s = tacc[mf][half_];
                s += __shfl_xor_sync(0xffffffffu, s, 1);
                s += __shfl_xor_sync(0xffffffffu, s, 2);
                if (tig == 0) rsum[warp >> 1][wm + mf * 16 + half_ * 8 + g] = s;
            }
        __syncthreads();
        if (tid < BMT) {
            float t = rsum[0][tid] + rsum[1][tid] + rsum[2][tid] + rsum[3][tid];
            g_tracep[(size_t)blockIdx.x * BB + m0 + tid] = t;
        }
        return;
    }

#pragma unroll
    for (int mf = 0; mf < 2; mf++)
#pragma unroll
        for (int ns = 0; ns < 4; ns++) {
            int col = n0 + wn + ns * 8 + tig * 2;
            int r0 = m0 + wm + mf * 16 + g;
#pragma unroll
            for (int half_ = 0; half_ < 2; half_++) {
                int r = r0 + half_ * 8;
                float v0 = cp[mf][ns][half_ * 2 + 0];
                float v1 = cp[mf][ns][half_ * 2 + 1];
                if (EPI == E_T1 || EPI == E_Y) {
                    __half* dst = (EPI == E_T1) ? g_T1 : g_Y;
                    size_t idx = (size_t)r * HH + col;
                    *(uint32_t*)(dst + idx) = h2pack(v0, v1);
                } else {  // E_L1
                    size_t ob = (size_t)r * HH + col;
                    float h0 = tanhf(v0 + tval * w1t[col] + bias[col]);
                    float h1 = tanhf(v1 + tval * w1t[col + 1] + bias[col + 1]);
                    *(uint32_t*)(g_H1p + ob) = h2pack(h0, h1);
                    float t0, t1;
                    h2unpack(*(const uint32_t*)(g_T1 + ob), t0, t1);
                    float u0 = (1.f - h0 * h0) * t0;
                    float u1 = (1.f - h1 * h1) * t1;
                    *(uint32_t*)(g_H1t + ob) = h2pack(u0, u1);
                }
            }
        }
}

// ---------------- setup / output ----------------
__global__ void setup_k(const float* __restrict__ x, const float* __restrict__ eps,
                        const float* __restrict__ W1, const float* __restrict__ W2,
                        const float* __restrict__ W3) {
    int i = blockIdx.x * blockDim.x + threadIdx.x;
    if (i < BB * FF) {
        float v = x[i];
        g_xcur[i] = v;
        g_XS[i]  = __float2half(v);
        g_eps[i] = __float2half(eps[i]);   // +-1 exact
    }
    if (i < BB) g_logdet[i] = 0.f;
    if (i < FF * HH) {                 // W1 rows 0..127
        int k = i / HH, n = i % HH;
        float w = W1[i];
        __half wh = __float2half(w);
        __half wl = __float2half(w - __half2float(wh));
        g_W1x[(size_t)k * HH + n]        = wh;    // exact split (T1)
        g_W1x[(size_t)(k + FF) * HH + n] = wl;
        g_W1h[(size_t)k * HH + n]        = wh;    // hi-only (per-stage L1)
    }
    if (i < HH * HH) {                 // W2 hi only
        g_W2x[i] = __float2half(W2[i]);
    }
    if (i < HH * FF) {                 // W3 [1024][128]
        int r3 = i / FF, c3 = i % FF;
        float w = W3[i];
        __half wh = __float2half(w);
        __half wl = __float2half(w - __half2float(wh));
        g_W3h[(size_t)r3 * FF + c3]          = wh;   // hi-only (per-stage L3)
        g_W3T[(size_t)c3 * HH + r3]          = wh;   // exact split (Y)
        g_W3T[(size_t)(c3 + FF) * HH + r3]   = wl;
    }
}

__global__ void finish_k(float* __restrict__ out) {
    int i = blockIdx.x * blockDim.x + threadIdx.x;
    if (i < BB * FF) out[i] = g_xcur[i];
    if (i < BB) out[BB * FF + i] = g_logdet[i];
}

// ---------------- launch ----------------
extern "C" void kernel_launch(void* const* d_in, const int* in_sizes, int n_in,
                              void* d_out, int out_size) {
    const float* x   = (const float*)d_in[0];
    const float* eps = (const float*)d_in[1];
    const float* W1  = (const float*)d_in[2];
    const float* b1  = (const float*)d_in[3];
    const float* W2  = (const float*)d_in[4];
    const float* b2  = (const float*)d_in[5];
    const float* W3  = (const float*)d_in[6];
    const float* b3  = (const float*)d_in[7];
    float* out = (float*)d_out;

    static bool attr_done = false;
    if (!attr_done) {
        cudaFuncSetAttribute(gemm_k<E_T1>,  cudaFuncAttributeMaxDynamicSharedMemorySize, SM_SINGLE);
        cudaFuncSetAttribute(gemm_k<E_Y>,   cudaFuncAttributeMaxDynamicSharedMemorySize, SM_SINGLE);
        cudaFuncSetAttribute(gemm_k<E_L1>,  cudaFuncAttributeMaxDynamicSharedMemorySize, SM_SINGLE);
        cudaFuncSetAttribute(gemm_k<E_L2F>, cudaFuncAttributeMaxDynamicSharedMemorySize, SM_DUAL);
        cudaFuncSetAttribute(gemm_k<E_L3P>, cudaFuncAttributeMaxDynamicSharedMemorySize, SM_SINGLE);
        attr_done = true;
    }

    const int ew = (BB * FF + 255) / 256;
    setup_k<<<ew, 256>>>(x, eps, W1, W2, W3);

    const float h = 1.0f / NSTEPS;
    const float stc[4] = {0.f, 0.5f, 0.5f, 1.f};
    const float* w1t = W1 + FF * HH;   // W1 row 128 (time column), fp32

    // Constants: T1 = eps @ W1, Y = eps @ W3^T (exact weights via hi;lo split)
    gemm_k<E_T1><<<dim3(8, BB / BMT), 256, SM_SINGLE>>>(nullptr, nullptr, 0.f, h, 0);
    gemm_k<E_Y> <<<dim3(8, BB / BMT), 256, SM_SINGLE>>>(nullptr, nullptr, 0.f, h, 0);

    for (int s = 0; s < NSTEPS; s++) {
        float t0 = s * h;
        for (int st = 0; st < 4; st++) {
            float tv = t0 + stc[st] * h;
            gemm_k<E_L1> <<<dim3(8, BB / BMT), 256, SM_SINGLE>>>(b1, w1t, tv, h, st);
            gemm_k<E_L2F><<<dim3(8, BB / BMT), 256, SM_DUAL>>>(b2, nullptr, 0.f, h, st);
            gemm_k<E_L3P><<<dim3(1, BB / BMT), 256, SM_SINGLE>>>(b3, nullptr, 0.f, h, st);
        }
    }
    finish_k<<<ew, 256>>>(out);
}

// round 17
// speedup vs baseline: 3.2245x; 1.4863x over previous
#include <cuda_runtime.h>
#include <cuda_fp16.h>
#include <cstdint>

// Problem dims
#define BB 16384
#define FF 128
#define HH 1024
#define NSTEPS 2

// ---------------- scratch (static __device__, no allocation) ----------------
// Weights [K][N] row-major
__device__ __align__(16) __half g_W1x[256 * HH];           // [256][1024] hi;lo (T1 only)
__device__ __align__(16) __half g_W1h[128 * HH];           // [128][1024] hi (per-stage L1)
__device__ __align__(16) __half g_W2x[(size_t)HH * HH];    // [1024][1024] hi only
__device__ __align__(16) __half g_W3h[(size_t)HH * FF];    // [1024][128] hi (per-stage L3)
__device__ __align__(16) __half g_W3T[256 * HH];           // [256][1024] hi;lo of W3^T (Y only)
// Activations, single copies
__device__ __align__(16) __half g_eps[(size_t)BB * FF];
__device__ __align__(16) __half g_XS [(size_t)BB * FF];
__device__ __align__(16) __half g_H1p[(size_t)BB * HH];
__device__ __align__(16) __half g_H1t[(size_t)BB * HH];
__device__ __align__(16) __half g_H2p[(size_t)BB * HH];
// constants for the tangent path, fp16
__device__ __align__(16) __half g_T1[(size_t)BB * HH];     // eps @ W1 (exact weights)
__device__ __align__(16) __half g_Y [(size_t)BB * HH];     // eps @ W3^T (exact weights)
// fp32 state
__device__ float g_tracep[(size_t)8 * BB]; // per-n-CTA trace partials (deterministic)
__device__ float g_xcur[BB * FF];
__device__ float g_accX[BB * FF];
__device__ float g_accL[BB];
__device__ float g_logdet[BB];

// ---------------- helpers ----------------
__device__ __forceinline__ uint32_t smem_u32(const void* p) {
    return (uint32_t)__cvta_generic_to_shared(p);
}
__device__ __forceinline__ void cp16(uint32_t s, const void* g) {
    asm volatile("cp.async.cg.shared.global [%0], [%1], 16;\n" :: "r"(s), "l"(g));
}
__device__ __forceinline__ void cp_commit() { asm volatile("cp.async.commit_group;\n"); }
__device__ __forceinline__ void cp_wait0()  { asm volatile("cp.async.wait_group 0;\n"); }
__device__ __forceinline__ void cp_wait1()  { asm volatile("cp.async.wait_group 1;\n"); }

__device__ __forceinline__ void ldsm4(uint32_t* r, uint32_t a) {
    asm volatile("ldmatrix.sync.aligned.m8n8.x4.shared.b16 {%0,%1,%2,%3},[%4];"
                 : "=r"(r[0]), "=r"(r[1]), "=r"(r[2]), "=r"(r[3]) : "r"(a));
}
__device__ __forceinline__ void ldsm4t(uint32_t* r, uint32_t a) {
    asm volatile("ldmatrix.sync.aligned.m8n8.x4.trans.shared.b16 {%0,%1,%2,%3},[%4];"
                 : "=r"(r[0]), "=r"(r[1]), "=r"(r[2]), "=r"(r[3]) : "r"(a));
}
__device__ __forceinline__ void mma16816(float* c, const uint32_t* a, uint32_t b0, uint32_t b1) {
    asm volatile(
        "mma.sync.aligned.m16n8k16.row.col.f32.f16.f16.f32 "
        "{%0,%1,%2,%3},{%4,%5,%6,%7},{%8,%9},{%0,%1,%2,%3};"
        : "+f"(c[0]), "+f"(c[1]), "+f"(c[2]), "+f"(c[3])
        : "r"(a[0]), "r"(a[1]), "r"(a[2]), "r"(a[3]), "r"(b0), "r"(b1));
}
__device__ __forceinline__ uint32_t h2pack(float a, float b) {
    __half2 t = __floats2half2_rn(a, b);
    return *reinterpret_cast<uint32_t*>(&t);
}
__device__ __forceinline__ void h2unpack(uint32_t v, float& a, float& b) {
    __half2 t = *reinterpret_cast<__half2*>(&v);
    a = __half2float(__low2half(t));
    b = __half2float(__high2half(t));
}

// ---------------- kernel ids ----------------
enum { E_T1 = 0, E_Y, E_L1, E_L2F, E_L3P };

// ---------------- fused GEMM core ----------------
// BMT=64, BN=128, BK=64, 256 threads, 8 warps (2 x 4), warp tile 32x32.
constexpr int BMT = 64, BN = 128, BK = 64, NSTG = 3;
constexpr int LDA_S = BK + 8;          // 72
constexpr int LDB_S = BN + 8;          // 136
constexpr int A_STG = BMT * LDA_S;     // 4608
constexpr int B_STG = BK * LDB_S;      // 8704
constexpr int SM_SINGLE = NSTG * (A_STG + B_STG) * 2;       // 79872 B
constexpr int SM_DUAL   = NSTG * (2 * A_STG + B_STG) * 2;   // 107520 B

template <int EPI>
__global__ __launch_bounds__(256, 2)
void gemm_k(const float* __restrict__ bias, const float* __restrict__ w1t,
            float tval, float h, int st) {
    constexpr bool DUAL = (EPI == E_L2F);
    constexpr int Nd = (EPI == E_L3P) ? FF : HH;
    constexpr int Kd = (EPI == E_T1 || EPI == E_Y) ? 256 :
                       (EPI == E_L1) ? 128 : 1024;            // logical K
    constexpr int LDA_G = (EPI == E_T1 || EPI == E_Y || EPI == E_L1) ? FF : HH;
    constexpr int KMASK = LDA_G - 1;

    const __half* Ap =
        (EPI == E_T1 || EPI == E_Y) ? g_eps :
        (EPI == E_L1) ? g_XS :
        (EPI == E_L2F) ? g_H1p : g_H2p;
    const __half* At = g_H1t;                                  // DUAL only
    const __half* Bg =
        (EPI == E_T1) ? g_W1x :
        (EPI == E_Y)  ? g_W3T :
        (EPI == E_L1) ? g_W1h :
        (EPI == E_L2F) ? g_W2x : g_W3h;

    extern __shared__ __align__(16) __half smdyn[];
    __half* sAp = smdyn;                                   // [NSTG][64][72]
    __half* sAt = smdyn + NSTG * A_STG;                    // DUAL only
    __half* sB  = smdyn + (DUAL ? 2 : 1) * NSTG * A_STG;   // [NSTG][64][136]
    __shared__ float rsum[4][BMT];

    const int tid = threadIdx.x, lane = tid & 31, warp = tid >> 5;
    const int m0 = blockIdx.y * BMT, n0 = blockIdx.x * BN;
    const int wm = (warp & 1) * 32, wn = (warp >> 1) * 32;

    float cp[2][4][4];
    float ct[DUAL ? 2 : 1][4][4];
#pragma unroll
    for (int i = 0; i < 2; i++)
#pragma unroll
        for (int j = 0; j < 4; j++)
#pragma unroll
            for (int k = 0; k < 4; k++) {
                cp[i][j][k] = 0.f;
                if (DUAL) ct[i][j][k] = 0.f;
            }

    auto pf = [&](int kt, int bufi) {
        const int k0 = kt * BK;
        __half* dAp = sAp + bufi * A_STG;
        __half* dB  = sB + bufi * B_STG;
#pragma unroll
        for (int i = 0; i < 2; i++) {          // A: 512 chunks of 8 halves
            int ch = tid + 256 * i;
            int r = ch >> 3, c8 = (ch & 7) * 8;
            int kg = (k0 + c8) & KMASK;
            cp16(smem_u32(dAp + r * LDA_S + c8), Ap + (size_t)(m0 + r) * LDA_G + kg);
            if (DUAL)
                cp16(smem_u32(sAt + bufi * A_STG + r * LDA_S + c8),
                     At + (size_t)(m0 + r) * LDA_G + kg);
        }
#pragma unroll
        for (int i = 0; i < 4; i++) {          // B: 1024 chunks
            int ch = tid + 256 * i;
            int r = ch >> 4, c8 = (ch & 15) * 8;
            cp16(smem_u32(dB + r * LDB_S + c8), Bg + (size_t)(k0 + r) * Nd + n0 + c8);
        }
        cp_commit();
    };

    const int nk = Kd / BK;
    pf(0, 0);
    if (nk > 1) pf(1, 1);
    for (int kt = 0; kt < nk; kt++) {
        const int buf = kt % NSTG;
        if (kt == nk - 1) cp_wait0(); else cp_wait1();
        __syncthreads();
        if (kt + 2 < nk) pf(kt + 2, (kt + 2) % NSTG);

        const __half* cAp = sAp + buf * A_STG;
        const __half* cAt = sAt + buf * A_STG;
        const __half* cB  = sB + buf * B_STG;
#pragma unroll
        for (int kk = 0; kk < BK; kk += 16) {
            uint32_t a[2][4], at_[DUAL ? 2 : 1][4], b[2][4];
#pragma unroll
            for (int mf = 0; mf < 2; mf++) {
                uint32_t off = (wm + mf * 16 + (lane & 15)) * LDA_S + kk + ((lane >> 4) << 3);
                ldsm4(a[mf], smem_u32(cAp + off));
                if (DUAL) ldsm4(at_[mf], smem_u32(cAt + off));
            }
#pragma unroll
            for (int nb = 0; nb < 2; nb++)
                ldsm4t(b[nb], smem_u32(cB + (kk + (lane & 7) + ((lane >> 3) & 1) * 8) * LDB_S
                                          + wn + nb * 16 + ((lane >> 4) << 3)));
#pragma unroll
            for (int mf = 0; mf < 2; mf++)
#pragma unroll
                for (int ns = 0; ns < 4; ns++) {
                    mma16816(cp[mf][ns], a[mf], b[ns >> 1][(ns & 1) * 2],
                             b[ns >> 1][(ns & 1) * 2 + 1]);
                    if (DUAL)
                        mma16816(ct[mf][ns], at_[mf], b[ns >> 1][(ns & 1) * 2],
                                 b[ns >> 1][(ns & 1) * 2 + 1]);
                }
        }
    }

    // ---------------- epilogues ----------------
    const int g = lane >> 2, tig = lane & 3;

    if (EPI == E_L3P) {
        // RK logdet update from completed trace partials (written by L2F)
        if (tid < BMT) {
            int row = m0 + tid;
            float tr = 0.f;
#pragma unroll
            for (int cix = 0; cix < 8; cix++) tr += g_tracep[(size_t)cix * BB + row];
            if (st == 0)      g_accL[row] = tr;
            else if (st < 3)  g_accL[row] += 2.f * tr;
            else              g_logdet[row] -= (h / 6.f) * (g_accL[row] + tr);
        }
        // primal dx + fused RK state update
#pragma unroll
        for (int mf = 0; mf < 2; mf++)
#pragma unroll
            for (int ns = 0; ns < 4; ns++) {
                int col = wn + ns * 8 + tig * 2;
                int r0 = m0 + wm + mf * 16 + g;
#pragma unroll
                for (int half_ = 0; half_ < 2; half_++) {
                    int r = r0 + half_ * 8;
#pragma unroll
                    for (int j = 0; j < 2; j++) {
                        float k = cp[mf][ns][half_ * 2 + j] + bias[col + j];
                        size_t i = (size_t)r * FF + col + j;
                        float xc = g_xcur[i];
                        float xs;
                        if (st == 0)      { g_accX[i] = k;         xs = xc + 0.5f * h * k; }
                        else if (st == 1) { g_accX[i] += 2.f * k;  xs = xc + 0.5f * h * k; }
                        else if (st == 2) { g_accX[i] += 2.f * k;  xs = xc + h * k; }
                        else {
                            float xn = xc + (h / 6.f) * (g_accX[i] + k);
                            g_xcur[i] = xn;
                            xs = xn;
                        }
                        g_XS[i] = __float2half(xs);
                    }
                }
            }
        return;
    }

    if (EPI == E_L2F) {
        float tacc[2][2] = {{0.f, 0.f}, {0.f, 0.f}};
#pragma unroll
        for (int mf = 0; mf < 2; mf++)
#pragma unroll
            for (int ns = 0; ns < 4; ns++) {
                int col = n0 + wn + ns * 8 + tig * 2;
                int r0 = m0 + wm + mf * 16 + g;
#pragma unroll
                for (int half_ = 0; half_ < 2; half_++) {
                    int r = r0 + half_ * 8;
                    size_t ob = (size_t)r * HH + col;
                    float h0 = tanhf(cp[mf][ns][half_ * 2 + 0] + bias[col]);
                    float h1 = tanhf(cp[mf][ns][half_ * 2 + 1] + bias[col + 1]);
                    *(uint32_t*)(g_H2p + ob) = h2pack(h0, h1);
                    float u0 = ct[mf][ns][half_ * 2 + 0] * (1.f - h0 * h0);
                    float u1 = ct[mf][ns][half_ * 2 + 1] * (1.f - h1 * h1);
                    float y0, y1;
                    h2unpack(*(const uint32_t*)(g_Y + ob), y0, y1);
                    tacc[mf][half_] += u0 * y0 + u1 * y1;
                }
            }
        // deterministic trace reduction: quad-shfl -> shared -> global partial
#pragma unroll
        for (int mf = 0; mf < 2; mf++)
#pragma unroll
            for (int half_ = 0; half_ < 2; half_++) {
                float s = tacc[mf][half_];
                s += __shfl_xor_sync(0xffffffffu, s, 1);
                s += __shfl_xor_sync(0xffffffffu, s, 2);
                if (tig == 0) rsum[warp >> 1][wm + mf * 16 + half_ * 8 + g] = s;
            }
        __syncthreads();
        if (tid < BMT) {
            float t = rsum[0][tid] + rsum[1][tid] + rsum[2][tid] + rsum[3][tid];
            g_tracep[(size_t)blockIdx.x * BB + m0 + tid] = t;
        }
        return;
    }

#pragma unroll
    for (int mf = 0; mf < 2; mf++)
#pragma unroll
        for (int ns = 0; ns < 4; ns++) {
            int col = n0 + wn + ns * 8 + tig * 2;
            int r0 = m0 + wm + mf * 16 + g;
#pragma unroll
            for (int half_ = 0; half_ < 2; half_++) {
                int r = r0 + half_ * 8;
                float v0 = cp[mf][ns][half_ * 2 + 0];
                float v1 = cp[mf][ns][half_ * 2 + 1];
                if (EPI == E_T1 || EPI == E_Y) {
                    __half* dst = (EPI == E_T1) ? g_T1 : g_Y;
                    size_t idx = (size_t)r * HH + col;
                    *(uint32_t*)(dst + idx) = h2pack(v0, v1);
                } else {  // E_L1
                    size_t ob = (size_t)r * HH + col;
                    float h0 = tanhf(v0 + tval * w1t[col] + bias[col]);
                    float h1 = tanhf(v1 + tval * w1t[col + 1] + bias[col + 1]);
                    *(uint32_t*)(g_H1p + ob) = h2pack(h0, h1);
                    float t0, t1;
                    h2unpack(*(const uint32_t*)(g_T1 + ob), t0, t1);
                    float u0 = (1.f - h0 * h0) * t0;
                    float u1 = (1.f - h1 * h1) * t1;
                    *(uint32_t*)(g_H1t + ob) = h2pack(u0, u1);
                }
            }
        }
}

// ---------------- setup / output ----------------
__global__ void setup_k(const float* __restrict__ x, const float* __restrict__ eps,
                        const float* __restrict__ W1, const float* __restrict__ W2,
                        const float* __restrict__ W3) {
    int i = blockIdx.x * blockDim.x + threadIdx.x;
    if (i < BB * FF) {
        float v = x[i];
        g_xcur[i] = v;
        g_XS[i]  = __float2half(v);
        g_eps[i] = __float2half(eps[i]);   // +-1 exact
    }
    if (i < BB) g_logdet[i] = 0.f;
    if (i < FF * HH) {                 // W1 rows 0..127
        int k = i / HH, n = i % HH;
        float w = W1[i];
        __half wh = __float2half(w);
        __half wl = __float2half(w - __half2float(wh));
        g_W1x[(size_t)k * HH + n]        = wh;    // exact split (T1)
        g_W1x[(size_t)(k + FF) * HH + n] = wl;
        g_W1h[(size_t)k * HH + n]        = wh;    // hi-only (per-stage L1)
    }
    if (i < HH * HH) {                 // W2 hi only
        g_W2x[i] = __float2half(W2[i]);
    }
    if (i < HH * FF) {                 // W3 [1024][128]
        int r3 = i / FF, c3 = i % FF;
        float w = W3[i];
        __half wh = __float2half(w);
        __half wl = __float2half(w - __half2float(wh));
        g_W3h[(size_t)r3 * FF + c3]          = wh;   // hi-only (per-stage L3)
        g_W3T[(size_t)c3 * HH + r3]          = wh;   // exact split (Y)
        g_W3T[(size_t)(c3 + FF) * HH + r3]   = wl;
    }
}

__global__ void finish_k(float* __restrict__ out) {
    int i = blockIdx.x * blockDim.x + threadIdx.x;
    if (i < BB * FF) out[i] = g_xcur[i];
    if (i < BB) out[BB * FF + i] = g_logdet[i];
}

// ---------------- launch ----------------
extern "C" void kernel_launch(void* const* d_in, const int* in_sizes, int n_in,
                              void* d_out, int out_size) {
    const float* x   = (const float*)d_in[0];
    const float* eps = (const float*)d_in[1];
    const float* W1  = (const float*)d_in[2];
    const float* b1  = (const float*)d_in[3];
    const float* W2  = (const float*)d_in[4];
    const float* b2  = (const float*)d_in[5];
    const float* W3  = (const float*)d_in[6];
    const float* b3  = (const float*)d_in[7];
    float* out = (float*)d_out;

    static bool attr_done = false;
    if (!attr_done) {
        cudaFuncSetAttribute(gemm_k<E_T1>,  cudaFuncAttributeMaxDynamicSharedMemorySize, SM_SINGLE);
        cudaFuncSetAttribute(gemm_k<E_Y>,   cudaFuncAttributeMaxDynamicSharedMemorySize, SM_SINGLE);
        cudaFuncSetAttribute(gemm_k<E_L1>,  cudaFuncAttributeMaxDynamicSharedMemorySize, SM_SINGLE);
        cudaFuncSetAttribute(gemm_k<E_L2F>, cudaFuncAttributeMaxDynamicSharedMemorySize, SM_DUAL);
        cudaFuncSetAttribute(gemm_k<E_L3P>, cudaFuncAttributeMaxDynamicSharedMemorySize, SM_SINGLE);
        attr_done = true;
    }

    const int ew = (BB * FF + 255) / 256;
    setup_k<<<ew, 256>>>(x, eps, W1, W2, W3);

    const float h = 1.0f / NSTEPS;
    const float stc[4] = {0.f, 0.5f, 0.5f, 1.f};
    const float* w1t = W1 + FF * HH;   // W1 row 128 (time column), fp32

    // Constants: T1 = eps @ W1, Y = eps @ W3^T (exact weights via hi;lo split)
    gemm_k<E_T1><<<dim3(8, BB / BMT), 256, SM_SINGLE>>>(nullptr, nullptr, 0.f, h, 0);
    gemm_k<E_Y> <<<dim3(8, BB / BMT), 256, SM_SINGLE>>>(nullptr, nullptr, 0.f, h, 0);

    for (int s = 0; s < NSTEPS; s++) {
        float t0 = s * h;
        for (int st = 0; st < 4; st++) {
            float tv = t0 + stc[st] * h;
            gemm_k<E_L1> <<<dim3(8, BB / BMT), 256, SM_SINGLE>>>(b1, w1t, tv, h, st);
            gemm_k<E_L2F><<<dim3(8, BB / BMT), 256, SM_DUAL>>>(b2, nullptr, 0.f, h, st);
            gemm_k<E_L3P><<<dim3(1, BB / BMT), 256, SM_SINGLE>>>(b3, nullptr, 0.f, h, st);
        }
    }
    finish_k<<<ew, 256>>>(out);
}